// round 1
// baseline (speedup 1.0000x reference)
#include <cuda_runtime.h>
#include <cuda_bf16.h>
#include <math.h>

// Problem constants
#define BB 2
#define SS 2048
#define DM 1024
#define HH 16
#define HD 64
#define DF 4096
#define NTOK (BB * SS)          // 4096
#define NEGV (-1e9f)
#define EPS 1e-6f

// ---------------------------------------------------------------------------
// Scratch (device globals — no allocation allowed)
// ---------------------------------------------------------------------------
__device__ float g_n1[NTOK * DM];
__device__ float g_q[NTOK * DM];
__device__ float g_k[NTOK * DM];
__device__ float g_v[NTOK * DM];
__device__ float g_scores[(long)BB * HH * SS * SS];   // 512 MB, reused as probs
__device__ float g_attn[NTOK * DM];
__device__ float g_h[NTOK * DM];
__device__ float g_n2[NTOK * DM];
__device__ float g_ffn[(long)NTOK * DF];

// ---------------------------------------------------------------------------
// LayerNorm (torch semantics: unbiased std (ddof=1), eps added to std,
// scalar alpha/beta)
// One block (256 threads) per row of 1024.
// ---------------------------------------------------------------------------
__global__ __launch_bounds__(256) void ln_kernel(const float* __restrict__ x,
                                                 const float* __restrict__ alpha,
                                                 const float* __restrict__ beta,
                                                 float* __restrict__ out) {
    long row = blockIdx.x;
    const float4* xr = (const float4*)(x + row * DM);
    float4 v = xr[threadIdx.x];

    float s  = v.x + v.y + v.z + v.w;
    float ss = v.x * v.x + v.y * v.y + v.z * v.z + v.w * v.w;

    // block reduce (sum, sumsq)
    __shared__ float sa[8], sb[8];
#pragma unroll
    for (int o = 16; o > 0; o >>= 1) {
        s  += __shfl_xor_sync(0xffffffffu, s, o);
        ss += __shfl_xor_sync(0xffffffffu, ss, o);
    }
    if ((threadIdx.x & 31) == 0) { sa[threadIdx.x >> 5] = s; sb[threadIdx.x >> 5] = ss; }
    __syncthreads();
    s = 0.f; ss = 0.f;
#pragma unroll
    for (int i = 0; i < 8; i++) { s += sa[i]; ss += sb[i]; }

    float mean = s * (1.0f / DM);
    float var  = (ss - (float)DM * mean * mean) * (1.0f / (DM - 1));
    var = fmaxf(var, 0.0f);
    float inv  = alpha[0] / (sqrtf(var) + EPS);
    float bta  = beta[0];

    float4 o;
    o.x = (v.x - mean) * inv + bta;
    o.y = (v.y - mean) * inv + bta;
    o.z = (v.z - mean) * inv + bta;
    o.w = (v.w - mean) * inv + bta;
    ((float4*)(out + row * DM))[threadIdx.x] = o;
}

// ---------------------------------------------------------------------------
// Masked softmax over rows of length 2048 (in place).
// grid.x = B*H*S rows; 256 threads, 8 elems each (strided -> coalesced).
// ---------------------------------------------------------------------------
__global__ __launch_bounds__(256) void softmax_kernel(float* __restrict__ p,
                                                      const int* __restrict__ mask) {
    long z = blockIdx.x;                 // b*H*S + h*S + sq
    float* row = p + z * (long)SS;
    int b = (int)(z >> 15);              // z / (H*S) = z / 32768
    const int* m = mask + (long)b * SS;
    int t = threadIdx.x;

    float vals[8];
    float mx = -INFINITY;
#pragma unroll
    for (int i = 0; i < 8; i++) {
        int col = t + i * 256;
        float v = row[col];
        v = (m[col] == 0) ? NEGV : v;
        vals[i] = v;
        mx = fmaxf(mx, v);
    }

    __shared__ float sm[8];
#pragma unroll
    for (int o = 16; o > 0; o >>= 1) mx = fmaxf(mx, __shfl_xor_sync(0xffffffffu, mx, o));
    if ((t & 31) == 0) sm[t >> 5] = mx;
    __syncthreads();
    mx = sm[0];
#pragma unroll
    for (int i = 1; i < 8; i++) mx = fmaxf(mx, sm[i]);
    __syncthreads();

    float sum = 0.f;
#pragma unroll
    for (int i = 0; i < 8; i++) {
        vals[i] = __expf(vals[i] - mx);
        sum += vals[i];
    }
#pragma unroll
    for (int o = 16; o > 0; o >>= 1) sum += __shfl_xor_sync(0xffffffffu, sum, o);
    if ((t & 31) == 0) sm[t >> 5] = sum;
    __syncthreads();
    sum = 0.f;
#pragma unroll
    for (int i = 0; i < 8; i++) sum += sm[i];

    float inv = 1.0f / sum;
#pragma unroll
    for (int i = 0; i < 8; i++) row[t + i * 256] = vals[i] * inv;
}

// ---------------------------------------------------------------------------
// Generic register-blocked SGEMM.
//   C[m,n] = alpha * sum_k A[m,k] * B(k,n)  (+bias[n]) (relu) (+res[m,n])
// TRANSB=false: B stored [K,N] row-major (ldb = row stride)
// TRANSB=true : B stored [N,K] row-major (ldb = row stride)   (q @ k^T case)
// Batched via blockIdx.z with (outer = z/16, inner = z%16) stride pairs;
// pass zeros for unbatched.
// All dims assumed divisible by tile sizes (true for this problem).
// ---------------------------------------------------------------------------
template <int BM, int BN, int BK, int TM, int TN, bool TRANSB, bool RELU, bool BIAS, bool RES>
__global__ __launch_bounds__((BM / TM) * (BN / TN)) void gemm_k(
    const float* __restrict__ A, const float* __restrict__ Bm,
    const float* __restrict__ bias, const float* __restrict__ res,
    float* __restrict__ C,
    int M, int N, int K, int lda, int ldb, int ldc,
    long sAo, long sAi, long sBo, long sBi, long sCo, long sCi,
    float alpha) {
    constexpr int THREADS = (BM / TM) * (BN / TN);

    __shared__ float As[BK][BM];
    __shared__ float Bs[BK][BN];

    int z = blockIdx.z;
    int zo = z >> 4, zi = z & 15;
    A  += (long)zo * sAo + (long)zi * sAi;
    Bm += (long)zo * sBo + (long)zi * sBi;
    C  += (long)zo * sCo + (long)zi * sCi;
    const float* Rp = RES ? (res + (long)zo * sCo + (long)zi * sCi) : nullptr;

    int bm = blockIdx.y * BM;
    int bn = blockIdx.x * BN;
    int tid = threadIdx.x;
    int tcol = tid % (BN / TN);
    int trow = tid / (BN / TN);

    float acc[TM][TN];
#pragma unroll
    for (int i = 0; i < TM; i++)
#pragma unroll
        for (int j = 0; j < TN; j++) acc[i][j] = 0.f;

    for (int k0 = 0; k0 < K; k0 += BK) {
        // A tile (transposed into smem)
#pragma unroll
        for (int i = tid; i < BM * BK; i += THREADS) {
            int r = i / BK, c = i % BK;
            As[c][r] = A[(long)(bm + r) * lda + (k0 + c)];
        }
        // B tile
        if (TRANSB) {
#pragma unroll
            for (int i = tid; i < BN * BK; i += THREADS) {
                int r = i / BK, c = i % BK;       // r over N
                Bs[c][r] = Bm[(long)(bn + r) * ldb + (k0 + c)];
            }
        } else {
#pragma unroll
            for (int i = tid; i < BK * BN; i += THREADS) {
                int c = i / BN, r = i % BN;       // c over K
                Bs[c][r] = Bm[(long)(k0 + c) * ldb + (bn + r)];
            }
        }
        __syncthreads();

#pragma unroll
        for (int kk = 0; kk < BK; kk++) {
            float a[TM], b[TN];
#pragma unroll
            for (int i = 0; i < TM; i++) a[i] = As[kk][trow * TM + i];
#pragma unroll
            for (int j = 0; j < TN; j++) b[j] = Bs[kk][tcol * TN + j];
#pragma unroll
            for (int i = 0; i < TM; i++)
#pragma unroll
                for (int j = 0; j < TN; j++) acc[i][j] += a[i] * b[j];
        }
        __syncthreads();
    }

#pragma unroll
    for (int i = 0; i < TM; i++) {
        int row = bm + trow * TM + i;
#pragma unroll
        for (int j = 0; j < TN; j++) {
            int col = bn + tcol * TN + j;
            float v = acc[i][j] * alpha;
            if (BIAS) v += bias[col];
            if (RELU) v = fmaxf(v, 0.f);
            if (RES)  v += Rp[(long)row * ldc + col];
            C[(long)row * ldc + col] = v;
        }
    }
}

// ---------------------------------------------------------------------------
// Host side
// ---------------------------------------------------------------------------
template <typename T>
static float* sym(const T& s) {
    void* p = nullptr;
    cudaGetSymbolAddress(&p, s);
    return (float*)p;
}

extern "C" void kernel_launch(void* const* d_in, const int* in_sizes, int n_in,
                              void* d_out, int out_size) {
    const float* x      = (const float*)d_in[0];
    const int*   mask   = (const int*)d_in[1];
    const float* Wq     = (const float*)d_in[2];
    const float* bq     = (const float*)d_in[3];
    const float* Wk     = (const float*)d_in[4];
    const float* bk     = (const float*)d_in[5];
    const float* Wv     = (const float*)d_in[6];
    const float* bv     = (const float*)d_in[7];
    const float* Wo     = (const float*)d_in[8];
    const float* bo     = (const float*)d_in[9];
    const float* W1     = (const float*)d_in[10];
    const float* b1     = (const float*)d_in[11];
    const float* W2     = (const float*)d_in[12];
    const float* b2     = (const float*)d_in[13];
    const float* alpha1 = (const float*)d_in[14];
    const float* beta1  = (const float*)d_in[15];
    const float* alpha2 = (const float*)d_in[16];
    const float* beta2  = (const float*)d_in[17];
    float* out = (float*)d_out;

    float* n1    = sym(g_n1);
    float* q     = sym(g_q);
    float* k     = sym(g_k);
    float* v     = sym(g_v);
    float* sc    = sym(g_scores);
    float* attn  = sym(g_attn);
    float* h     = sym(g_h);
    float* n2    = sym(g_n2);
    float* ffn   = sym(g_ffn);

    // 1. LN1
    ln_kernel<<<NTOK, 256>>>(x, alpha1, beta1, n1);

    // 2. QKV projections: [4096,1024] @ [1024,1024] + bias
    {
        dim3 grid(DM / 128, NTOK / 128, 1);
        gemm_k<128, 128, 16, 8, 8, false, false, true, false><<<grid, 256>>>(
            n1, Wq, bq, nullptr, q, NTOK, DM, DM, DM, DM, DM, 0, 0, 0, 0, 0, 0, 1.0f);
        gemm_k<128, 128, 16, 8, 8, false, false, true, false><<<grid, 256>>>(
            n1, Wk, bk, nullptr, k, NTOK, DM, DM, DM, DM, DM, 0, 0, 0, 0, 0, 0, 1.0f);
        gemm_k<128, 128, 16, 8, 8, false, false, true, false><<<grid, 256>>>(
            n1, Wv, bv, nullptr, v, NTOK, DM, DM, DM, DM, DM, 0, 0, 0, 0, 0, 0, 1.0f);
    }

    // 3. scores = q @ k^T / 8   (batched over b*H = 32)
    {
        dim3 grid(SS / 128, SS / 128, BB * HH);
        long sAo = (long)SS * DM, sAi = HD;                     // q: [b][s][h*64+d]
        long sCo = (long)HH * SS * SS, sCi = (long)SS * SS;     // scores: [b][h][sq][sk]
        gemm_k<128, 128, 16, 8, 8, true, false, false, false><<<grid, 256>>>(
            q, k, nullptr, nullptr, sc, SS, SS, HD, DM, DM, SS,
            sAo, sAi, sAo, sAi, sCo, sCi, 0.125f);
    }

    // 4. masked softmax in place
    softmax_kernel<<<(long)BB * HH * SS, 256>>>(sc, mask);

    // 5. attn = probs @ v  (batched, N = HD = 64)
    {
        dim3 grid(HD / 64, SS / 128, BB * HH);
        long sAo = (long)HH * SS * SS, sAi = (long)SS * SS;
        long sBo = (long)SS * DM, sBi = HD;
        gemm_k<128, 64, 16, 8, 4, false, false, false, false><<<grid, 256>>>(
            sc, v, nullptr, nullptr, attn, SS, HD, SS, SS, DM, DM,
            sAo, sAi, sBo, sBi, sBo, sBi, 1.0f);
    }

    // 6. h = x + attn @ Wo + bo
    {
        dim3 grid(DM / 128, NTOK / 128, 1);
        gemm_k<128, 128, 16, 8, 8, false, false, true, true><<<grid, 256>>>(
            attn, Wo, bo, x, h, NTOK, DM, DM, DM, DM, DM, 0, 0, 0, 0, 0, 0, 1.0f);
    }

    // 7. LN2
    ln_kernel<<<NTOK, 256>>>(h, alpha2, beta2, n2);

    // 8. ffn = relu(n2 @ W1 + b1)
    {
        dim3 grid(DF / 128, NTOK / 128, 1);
        gemm_k<128, 128, 16, 8, 8, false, true, true, false><<<grid, 256>>>(
            n2, W1, b1, nullptr, ffn, NTOK, DF, DM, DM, DF, DF, 0, 0, 0, 0, 0, 0, 1.0f);
    }

    // 9. out = h + ffn @ W2 + b2
    {
        dim3 grid(DM / 128, NTOK / 128, 1);
        gemm_k<128, 128, 16, 8, 8, false, false, true, true><<<grid, 256>>>(
            ffn, W2, b2, h, out, NTOK, DM, DF, DF, DM, DM, 0, 0, 0, 0, 0, 0, 1.0f);
    }
}

// round 2
// speedup vs baseline: 2.3597x; 2.3597x over previous
#include <cuda_runtime.h>
#include <cuda_bf16.h>
#include <math.h>
#include <stdint.h>

// Problem constants
#define BB 2
#define SS 2048
#define DM 1024
#define HH 16
#define HD 64
#define DF 4096
#define NTOK (BB * SS)          // 4096
#define NEGV (-1e9f)
#define EPS 1e-6f

// ---------------------------------------------------------------------------
// Scratch (device globals — no allocation allowed)
// ---------------------------------------------------------------------------
__device__ float g_n1[NTOK * DM];
__device__ float g_q[NTOK * DM];
__device__ float g_k[NTOK * DM];
__device__ float g_v[NTOK * DM];
__device__ float g_scores[(long)BB * HH * SS * SS];   // 512 MB, reused as probs
__device__ float g_attn[NTOK * DM];
__device__ float g_h[NTOK * DM];
__device__ float g_n2[NTOK * DM];
__device__ float g_ffn[(long)NTOK * DF];

// ---------------------------------------------------------------------------
// Helpers
// ---------------------------------------------------------------------------
__device__ __forceinline__ uint32_t f2tf(float f) {
    uint32_t u;
    asm("cvt.rna.tf32.f32 %0, %1;" : "=r"(u) : "f"(f));
    return u;
}
__device__ __forceinline__ uint4 cvt4(float4 v) {
    uint4 r;
    r.x = f2tf(v.x); r.y = f2tf(v.y); r.z = f2tf(v.z); r.w = f2tf(v.w);
    return r;
}
__device__ __forceinline__ void mma_tf32(float c[4], uint32_t a0, uint32_t a1,
                                         uint32_t a2, uint32_t a3,
                                         uint32_t b0, uint32_t b1) {
    asm volatile(
        "mma.sync.aligned.m16n8k8.row.col.f32.tf32.tf32.f32 "
        "{%0,%1,%2,%3}, {%4,%5,%6,%7}, {%8,%9}, {%0,%1,%2,%3};"
        : "+f"(c[0]), "+f"(c[1]), "+f"(c[2]), "+f"(c[3])
        : "r"(a0), "r"(a1), "r"(a2), "r"(a3), "r"(b0), "r"(b1));
}

// ---------------------------------------------------------------------------
// LayerNorm (torch semantics: unbiased std (ddof=1), eps added to std)
// ---------------------------------------------------------------------------
__global__ __launch_bounds__(256) void ln_kernel(const float* __restrict__ x,
                                                 const float* __restrict__ alpha,
                                                 const float* __restrict__ beta,
                                                 float* __restrict__ out) {
    long row = blockIdx.x;
    const float4* xr = (const float4*)(x + row * DM);
    float4 v = xr[threadIdx.x];

    float s  = v.x + v.y + v.z + v.w;
    float ss = v.x * v.x + v.y * v.y + v.z * v.z + v.w * v.w;

    __shared__ float sa[8], sb[8];
#pragma unroll
    for (int o = 16; o > 0; o >>= 1) {
        s  += __shfl_xor_sync(0xffffffffu, s, o);
        ss += __shfl_xor_sync(0xffffffffu, ss, o);
    }
    if ((threadIdx.x & 31) == 0) { sa[threadIdx.x >> 5] = s; sb[threadIdx.x >> 5] = ss; }
    __syncthreads();
    s = 0.f; ss = 0.f;
#pragma unroll
    for (int i = 0; i < 8; i++) { s += sa[i]; ss += sb[i]; }

    float mean = s * (1.0f / DM);
    float var  = (ss - (float)DM * mean * mean) * (1.0f / (DM - 1));
    var = fmaxf(var, 0.0f);
    float inv  = alpha[0] / (sqrtf(var) + EPS);
    float bta  = beta[0];

    float4 o;
    o.x = (v.x - mean) * inv + bta;
    o.y = (v.y - mean) * inv + bta;
    o.z = (v.z - mean) * inv + bta;
    o.w = (v.w - mean) * inv + bta;
    ((float4*)(out + row * DM))[threadIdx.x] = o;
}

// ---------------------------------------------------------------------------
// Masked softmax over rows of length 2048 (in place).
// ---------------------------------------------------------------------------
__global__ __launch_bounds__(256) void softmax_kernel(float* __restrict__ p,
                                                      const int* __restrict__ mask) {
    long z = blockIdx.x;
    float* row = p + z * (long)SS;
    int b = (int)(z >> 15);
    const int* m = mask + (long)b * SS;
    int t = threadIdx.x;

    float vals[8];
    float mx = -INFINITY;
#pragma unroll
    for (int i = 0; i < 8; i++) {
        int col = t + i * 256;
        float v = row[col];
        v = (m[col] == 0) ? NEGV : v;
        vals[i] = v;
        mx = fmaxf(mx, v);
    }

    __shared__ float sm[8];
#pragma unroll
    for (int o = 16; o > 0; o >>= 1) mx = fmaxf(mx, __shfl_xor_sync(0xffffffffu, mx, o));
    if ((t & 31) == 0) sm[t >> 5] = mx;
    __syncthreads();
    mx = sm[0];
#pragma unroll
    for (int i = 1; i < 8; i++) mx = fmaxf(mx, sm[i]);
    __syncthreads();

    float sum = 0.f;
#pragma unroll
    for (int i = 0; i < 8; i++) {
        vals[i] = __expf(vals[i] - mx);
        sum += vals[i];
    }
#pragma unroll
    for (int o = 16; o > 0; o >>= 1) sum += __shfl_xor_sync(0xffffffffu, sum, o);
    if ((t & 31) == 0) sm[t >> 5] = sum;
    __syncthreads();
    sum = 0.f;
#pragma unroll
    for (int i = 0; i < 8; i++) sum += sm[i];

    float inv = 1.0f / sum;
#pragma unroll
    for (int i = 0; i < 8; i++) row[t + i * 256] = vals[i] * inv;
}

// ---------------------------------------------------------------------------
// TF32 tensor-core GEMM.
//   C[m,n] = alpha * sum_k A[m,k] * B(k,n)  (+bias[n]) (relu) (+res[m,n])
// TRANSB=false: B stored [K,N] row-major.  TRANSB=true: B stored [N,K].
// BM=128, BN in {128,64}, BK=32.  256 threads, 8 warps.
// Smem layouts (conflict-free fragment reads):
//   As  [BM][36]         (row-major, k stride 36)
//   BsN [32][BN+8]       (normal B)
//   BsT [BN][36]         (transposed B, same pattern as A)
// ---------------------------------------------------------------------------
template <int BM, int BN, bool TRANSB, bool RELU, bool BIAS, bool RES>
__global__ __launch_bounds__(256) void mma_gemm(
    const float* __restrict__ A, const float* __restrict__ Bm,
    const float* __restrict__ bias, const float* __restrict__ res,
    float* __restrict__ C,
    int M, int N, int K, int lda, int ldb, int ldc,
    long sAo, long sAi, long sBo, long sBi, long sCo, long sCi,
    float alpha) {
    constexpr int BK = 32;
    constexpr int AS = 36;                 // padded k-stride
    constexpr int BSN = BN + 8;            // padded n-stride (normal B)
    constexpr int WARPS_N = BN / 32;       // 4 or 2
    constexpr int WARPS_M = 8 / WARPS_N;   // 2 or 4
    constexpr int WM = BM / WARPS_M;       // 64 or 32
    constexpr int MT = WM / 16;            // 4 or 2
    constexpr int NT = 4;                  // 32/8

    __shared__ uint32_t Asm[BM * AS];
    __shared__ uint32_t Bsm[TRANSB ? (BN * AS) : (BK * BSN)];

    int z = blockIdx.z;
    int zo = z >> 4, zi = z & 15;
    A  += (long)zo * sAo + (long)zi * sAi;
    Bm += (long)zo * sBo + (long)zi * sBi;
    C  += (long)zo * sCo + (long)zi * sCi;
    const float* Rp = RES ? (res + (long)zo * sCo + (long)zi * sCi) : nullptr;

    int bm = blockIdx.y * BM;
    int bn = blockIdx.x * BN;
    int tid  = threadIdx.x;
    int warp = tid >> 5;
    int lane = tid & 31;
    int g  = lane >> 2;
    int tg = lane & 3;
    int wm = warp / WARPS_N;
    int wn = warp % WARPS_N;

    float acc[MT][NT][4];
#pragma unroll
    for (int i = 0; i < MT; i++)
#pragma unroll
        for (int j = 0; j < NT; j++)
#pragma unroll
            for (int c = 0; c < 4; c++) acc[i][j][c] = 0.f;

    // global-load indices
    const int am = tid >> 3;          // 0..31
    const int ak = (tid & 7) * 4;     // 0..28
    constexpr int AITERS = BM / 32;

    constexpr int BCOLS = BN / 4;
    constexpr int BROWS = 256 / BCOLS;
    constexpr int BITERS_N = BK / BROWS;
    constexpr int BITERS_T = BN / 32;
    constexpr int BITERS = TRANSB ? BITERS_T : BITERS_N;
    const int bk_ = tid / BCOLS;          // normal: row within k-tile
    const int bn_ = (tid % BCOLS) * 4;    // normal: col
    // transB reuses am/ak pattern

    float4 aR[AITERS];
    float4 bR[BITERS];

    const int nTiles = K / BK;

    // prefetch tile 0
#pragma unroll
    for (int i = 0; i < AITERS; i++)
        aR[i] = *(const float4*)(A + (long)(bm + am + 32 * i) * lda + ak);
    if (TRANSB) {
#pragma unroll
        for (int i = 0; i < BITERS; i++)
            bR[i] = *(const float4*)(Bm + (long)(bn + am + 32 * i) * ldb + ak);
    } else {
#pragma unroll
        for (int i = 0; i < BITERS; i++)
            bR[i] = *(const float4*)(Bm + (long)(bk_ + BROWS * i) * ldb + bn + bn_);
    }
#pragma unroll
    for (int i = 0; i < AITERS; i++)
        *(uint4*)&Asm[(am + 32 * i) * AS + ak] = cvt4(aR[i]);
    if (TRANSB) {
#pragma unroll
        for (int i = 0; i < BITERS; i++)
            *(uint4*)&Bsm[(am + 32 * i) * AS + ak] = cvt4(bR[i]);
    } else {
#pragma unroll
        for (int i = 0; i < BITERS; i++)
            *(uint4*)&Bsm[(bk_ + BROWS * i) * BSN + bn_] = cvt4(bR[i]);
    }
    __syncthreads();

    for (int t = 0; t < nTiles; t++) {
        int k0n = (t + 1) * BK;
        if (t + 1 < nTiles) {
#pragma unroll
            for (int i = 0; i < AITERS; i++)
                aR[i] = *(const float4*)(A + (long)(bm + am + 32 * i) * lda + k0n + ak);
            if (TRANSB) {
#pragma unroll
                for (int i = 0; i < BITERS; i++)
                    bR[i] = *(const float4*)(Bm + (long)(bn + am + 32 * i) * ldb + k0n + ak);
            } else {
#pragma unroll
                for (int i = 0; i < BITERS; i++)
                    bR[i] = *(const float4*)(Bm + (long)(k0n + bk_ + BROWS * i) * ldb + bn + bn_);
            }
        }

        // compute 4 k8-steps
#pragma unroll
        for (int ks = 0; ks < 4; ks++) {
            uint32_t af[MT][4];
            uint32_t bf[NT][2];
#pragma unroll
            for (int mt = 0; mt < MT; mt++) {
                int r = wm * WM + mt * 16 + g;
                af[mt][0] = Asm[r * AS + ks * 8 + tg];
                af[mt][1] = Asm[(r + 8) * AS + ks * 8 + tg];
                af[mt][2] = Asm[r * AS + ks * 8 + tg + 4];
                af[mt][3] = Asm[(r + 8) * AS + ks * 8 + tg + 4];
            }
#pragma unroll
            for (int nt = 0; nt < NT; nt++) {
                int c = wn * 32 + nt * 8 + g;
                if (TRANSB) {
                    bf[nt][0] = Bsm[c * AS + ks * 8 + tg];
                    bf[nt][1] = Bsm[c * AS + ks * 8 + tg + 4];
                } else {
                    bf[nt][0] = Bsm[(ks * 8 + tg) * BSN + c];
                    bf[nt][1] = Bsm[(ks * 8 + tg + 4) * BSN + c];
                }
            }
#pragma unroll
            for (int mt = 0; mt < MT; mt++)
#pragma unroll
                for (int nt = 0; nt < NT; nt++)
                    mma_tf32(acc[mt][nt], af[mt][0], af[mt][1], af[mt][2], af[mt][3],
                             bf[nt][0], bf[nt][1]);
        }
        __syncthreads();

        if (t + 1 < nTiles) {
#pragma unroll
            for (int i = 0; i < AITERS; i++)
                *(uint4*)&Asm[(am + 32 * i) * AS + ak] = cvt4(aR[i]);
            if (TRANSB) {
#pragma unroll
                for (int i = 0; i < BITERS; i++)
                    *(uint4*)&Bsm[(am + 32 * i) * AS + ak] = cvt4(bR[i]);
            } else {
#pragma unroll
                for (int i = 0; i < BITERS; i++)
                    *(uint4*)&Bsm[(bk_ + BROWS * i) * BSN + bn_] = cvt4(bR[i]);
            }
            __syncthreads();
        }
    }

    // epilogue: each (mt,nt) frag covers rows {r, r+8}, cols {c, c+1}
#pragma unroll
    for (int mt = 0; mt < MT; mt++) {
        int r = bm + wm * WM + mt * 16 + g;
#pragma unroll
        for (int nt = 0; nt < NT; nt++) {
            int c = bn + wn * 32 + nt * 8 + tg * 2;
            float2 v0, v1;
            v0.x = acc[mt][nt][0] * alpha; v0.y = acc[mt][nt][1] * alpha;
            v1.x = acc[mt][nt][2] * alpha; v1.y = acc[mt][nt][3] * alpha;
            if (BIAS) {
                float2 bv = *(const float2*)(bias + c);
                v0.x += bv.x; v0.y += bv.y; v1.x += bv.x; v1.y += bv.y;
            }
            if (RELU) {
                v0.x = fmaxf(v0.x, 0.f); v0.y = fmaxf(v0.y, 0.f);
                v1.x = fmaxf(v1.x, 0.f); v1.y = fmaxf(v1.y, 0.f);
            }
            if (RES) {
                float2 r0 = *(const float2*)(Rp + (long)r * ldc + c);
                float2 r1 = *(const float2*)(Rp + (long)(r + 8) * ldc + c);
                v0.x += r0.x; v0.y += r0.y; v1.x += r1.x; v1.y += r1.y;
            }
            *(float2*)(C + (long)r * ldc + c) = v0;
            *(float2*)(C + (long)(r + 8) * ldc + c) = v1;
        }
    }
}

// ---------------------------------------------------------------------------
// Host side
// ---------------------------------------------------------------------------
template <typename T>
static float* sym(const T& s) {
    void* p = nullptr;
    cudaGetSymbolAddress(&p, s);
    return (float*)p;
}

extern "C" void kernel_launch(void* const* d_in, const int* in_sizes, int n_in,
                              void* d_out, int out_size) {
    const float* x      = (const float*)d_in[0];
    const int*   mask   = (const int*)d_in[1];
    const float* Wq     = (const float*)d_in[2];
    const float* bq     = (const float*)d_in[3];
    const float* Wk     = (const float*)d_in[4];
    const float* bk     = (const float*)d_in[5];
    const float* Wv     = (const float*)d_in[6];
    const float* bv     = (const float*)d_in[7];
    const float* Wo     = (const float*)d_in[8];
    const float* bo     = (const float*)d_in[9];
    const float* W1     = (const float*)d_in[10];
    const float* b1     = (const float*)d_in[11];
    const float* W2     = (const float*)d_in[12];
    const float* b2     = (const float*)d_in[13];
    const float* alpha1 = (const float*)d_in[14];
    const float* beta1  = (const float*)d_in[15];
    const float* alpha2 = (const float*)d_in[16];
    const float* beta2  = (const float*)d_in[17];
    float* out = (float*)d_out;

    float* n1   = sym(g_n1);
    float* q    = sym(g_q);
    float* k    = sym(g_k);
    float* v    = sym(g_v);
    float* sc   = sym(g_scores);
    float* attn = sym(g_attn);
    float* h    = sym(g_h);
    float* n2   = sym(g_n2);
    float* ffn  = sym(g_ffn);

    // 1. LN1
    ln_kernel<<<NTOK, 256>>>(x, alpha1, beta1, n1);

    // 2. QKV projections
    {
        dim3 grid(DM / 128, NTOK / 128, 1);
        mma_gemm<128, 128, false, false, true, false><<<grid, 256>>>(
            n1, Wq, bq, nullptr, q, NTOK, DM, DM, DM, DM, DM, 0, 0, 0, 0, 0, 0, 1.0f);
        mma_gemm<128, 128, false, false, true, false><<<grid, 256>>>(
            n1, Wk, bk, nullptr, k, NTOK, DM, DM, DM, DM, DM, 0, 0, 0, 0, 0, 0, 1.0f);
        mma_gemm<128, 128, false, false, true, false><<<grid, 256>>>(
            n1, Wv, bv, nullptr, v, NTOK, DM, DM, DM, DM, DM, 0, 0, 0, 0, 0, 0, 1.0f);
    }

    // 3. scores = q @ k^T / 8   (batched over b*H = 32), B transposed path
    {
        dim3 grid(SS / 128, SS / 128, BB * HH);
        long sAo = (long)SS * DM, sAi = HD;
        long sCo = (long)HH * SS * SS, sCi = (long)SS * SS;
        mma_gemm<128, 128, true, false, false, false><<<grid, 256>>>(
            q, k, nullptr, nullptr, sc, SS, SS, HD, DM, DM, SS,
            sAo, sAi, sAo, sAi, sCo, sCi, 0.125f);
    }

    // 4. masked softmax in place
    softmax_kernel<<<(long)BB * HH * SS, 256>>>(sc, mask);

    // 5. attn = probs @ v  (batched, N = HD = 64)
    {
        dim3 grid(HD / 64, SS / 128, BB * HH);
        long sAo = (long)HH * SS * SS, sAi = (long)SS * SS;
        long sBo = (long)SS * DM, sBi = HD;
        mma_gemm<128, 64, false, false, false, false><<<grid, 256>>>(
            sc, v, nullptr, nullptr, attn, SS, HD, SS, SS, DM, DM,
            sAo, sAi, sBo, sBi, sBo, sBi, 1.0f);
    }

    // 6. h = x + attn @ Wo + bo
    {
        dim3 grid(DM / 128, NTOK / 128, 1);
        mma_gemm<128, 128, false, false, true, true><<<grid, 256>>>(
            attn, Wo, bo, x, h, NTOK, DM, DM, DM, DM, DM, 0, 0, 0, 0, 0, 0, 1.0f);
    }

    // 7. LN2
    ln_kernel<<<NTOK, 256>>>(h, alpha2, beta2, n2);

    // 8. ffn = relu(n2 @ W1 + b1)
    {
        dim3 grid(DF / 128, NTOK / 128, 1);
        mma_gemm<128, 128, false, true, true, false><<<grid, 256>>>(
            n2, W1, b1, nullptr, ffn, NTOK, DF, DM, DM, DF, DF, 0, 0, 0, 0, 0, 0, 1.0f);
    }

    // 9. out = h + ffn @ W2 + b2
    {
        dim3 grid(DM / 128, NTOK / 128, 1);
        mma_gemm<128, 128, false, false, true, true><<<grid, 256>>>(
            ffn, W2, b2, h, out, NTOK, DM, DF, DF, DM, DM, 0, 0, 0, 0, 0, 0, 1.0f);
    }
}

// round 7
// speedup vs baseline: 4.1989x; 1.7794x over previous
#include <cuda_runtime.h>
#include <cuda_bf16.h>
#include <math.h>
#include <stdint.h>

// Problem constants
#define BB 2
#define SS 2048
#define DM 1024
#define HH 16
#define HD 64
#define DF 4096
#define NTOK (BB * SS)          // 4096
#define NEGV (-1e9f)
#define EPS 1e-6f

// ---------------------------------------------------------------------------
// Scratch (device globals — no allocation allowed)
// ---------------------------------------------------------------------------
__device__ float g_n1[NTOK * DM];
__device__ float g_qkv[(long)NTOK * 3 * DM];   // q|k|v interleaved per row
__device__ float g_wcat[DM * 3 * DM];          // Wq|Wk|Wv  [1024][3072]
__device__ float g_bcat[3 * DM];
__device__ float g_attn[NTOK * DM];
__device__ float g_h[NTOK * DM];
__device__ float g_n2[NTOK * DM];
__device__ float g_ffn[(long)NTOK * DF];

// ---------------------------------------------------------------------------
// Helpers
// ---------------------------------------------------------------------------
__device__ __forceinline__ uint32_t f2tf(float f) {
    uint32_t u;
    asm("cvt.rna.tf32.f32 %0, %1;" : "=r"(u) : "f"(f));
    return u;
}
__device__ __forceinline__ uint4 cvt4(float4 v) {
    uint4 r;
    r.x = f2tf(v.x); r.y = f2tf(v.y); r.z = f2tf(v.z); r.w = f2tf(v.w);
    return r;
}
__device__ __forceinline__ void mma_tf32(float c[4], uint32_t a0, uint32_t a1,
                                         uint32_t a2, uint32_t a3,
                                         uint32_t b0, uint32_t b1) {
    asm volatile(
        "mma.sync.aligned.m16n8k8.row.col.f32.tf32.tf32.f32 "
        "{%0,%1,%2,%3}, {%4,%5,%6,%7}, {%8,%9}, {%0,%1,%2,%3};"
        : "+f"(c[0]), "+f"(c[1]), "+f"(c[2]), "+f"(c[3])
        : "r"(a0), "r"(a1), "r"(a2), "r"(a3), "r"(b0), "r"(b1));
}

// ---------------------------------------------------------------------------
// Concat Wq|Wk|Wv and biases into contiguous [1024][3072] / [3072]
// ---------------------------------------------------------------------------
__global__ __launch_bounds__(256) void concat_w(
    const float* __restrict__ Wq, const float* __restrict__ Wk,
    const float* __restrict__ Wv, const float* __restrict__ bq,
    const float* __restrict__ bk, const float* __restrict__ bv,
    float* __restrict__ wcat, float* __restrict__ bcat) {
    long i = blockIdx.x * 256L + threadIdx.x;
    int row = (int)(i / (3 * DM));
    int col = (int)(i % (3 * DM));
    const float* W = (col < DM) ? Wq : ((col < 2 * DM) ? Wk : Wv);
    wcat[i] = W[row * DM + (col & (DM - 1))];
    if (i < 3 * DM) {
        const float* bb = (i < DM) ? bq : ((i < 2 * DM) ? bk : bv);
        bcat[i] = bb[i & (DM - 1)];
    }
}

// ---------------------------------------------------------------------------
// LayerNorm (torch semantics: unbiased std (ddof=1), eps added to std)
// ---------------------------------------------------------------------------
__global__ __launch_bounds__(256) void ln_kernel(const float* __restrict__ x,
                                                 const float* __restrict__ alpha,
                                                 const float* __restrict__ beta,
                                                 float* __restrict__ out) {
    long row = blockIdx.x;
    const float4* xr = (const float4*)(x + row * DM);
    float4 v = xr[threadIdx.x];

    float s  = v.x + v.y + v.z + v.w;
    float ss = v.x * v.x + v.y * v.y + v.z * v.z + v.w * v.w;

    __shared__ float sa[8], sb[8];
#pragma unroll
    for (int o = 16; o > 0; o >>= 1) {
        s  += __shfl_xor_sync(0xffffffffu, s, o);
        ss += __shfl_xor_sync(0xffffffffu, ss, o);
    }
    if ((threadIdx.x & 31) == 0) { sa[threadIdx.x >> 5] = s; sb[threadIdx.x >> 5] = ss; }
    __syncthreads();
    s = 0.f; ss = 0.f;
#pragma unroll
    for (int i = 0; i < 8; i++) { s += sa[i]; ss += sb[i]; }

    float mean = s * (1.0f / DM);
    float var  = (ss - (float)DM * mean * mean) * (1.0f / (DM - 1));
    var = fmaxf(var, 0.0f);
    float inv  = alpha[0] / (sqrtf(var) + EPS);
    float bta  = beta[0];

    float4 o;
    o.x = (v.x - mean) * inv + bta;
    o.y = (v.y - mean) * inv + bta;
    o.z = (v.z - mean) * inv + bta;
    o.w = (v.w - mean) * inv + bta;
    ((float4*)(out + row * DM))[threadIdx.x] = o;
}

// ---------------------------------------------------------------------------
// Flash attention (TF32 tensor cores, online softmax).
// grid: (S/128, H, B); 256 threads = 8 warps; each warp owns 16 Q rows.
// Q fragments loaded directly from gmem (no smem staging).
// Ksm: 64 rows, stride 76 (conflict-free S-MMA reads); doubles as the P
// staging area (8 warps x 16x36, max idx 4607 < 64*76=4864) AFTER the
// S-MMA — guarded by an extra __syncthreads.
// Vsm: 64 rows, stride 72 (conflict-free PV-MMA reads).
// P chunks are 16x32 (two halves) so stride 36 has no row aliasing.
// ---------------------------------------------------------------------------
__global__ __launch_bounds__(256) void flash_kernel(
    const float* __restrict__ qkv, const int* __restrict__ mask,
    float* __restrict__ out) {
    constexpr int LDQ = 3 * DM;
    constexpr int KS = 76;
    constexpr int VS = 72;
    int qb = blockIdx.x * 128;
    int h  = blockIdx.y;
    int b  = blockIdx.z;
    const float* qp = qkv + (long)b * SS * LDQ + h * HD;
    const float* kp = qp + DM;
    const float* vp = qp + 2 * DM;
    const int* mp = mask + b * SS;

    __shared__ uint32_t Ksm[64 * KS];   // K tile / P staging
    __shared__ uint32_t Vsm[64 * VS];
    __shared__ float mAdd[64];

    int tid = threadIdx.x, warp = tid >> 5, lane = tid & 31;
    int g = lane >> 2, tg = lane & 3;
    int rrow = qb + warp * 16 + g;

    // Q fragments straight from gmem (scaled by 1/sqrt(HD)=0.125, tf32)
    uint32_t qf[8][4];
#pragma unroll
    for (int ks = 0; ks < 8; ks++) {
        int c0 = ks * 8 + tg;
        qf[ks][0] = f2tf(0.125f * qp[(long)rrow * LDQ + c0]);
        qf[ks][1] = f2tf(0.125f * qp[(long)(rrow + 8) * LDQ + c0]);
        qf[ks][2] = f2tf(0.125f * qp[(long)rrow * LDQ + c0 + 4]);
        qf[ks][3] = f2tf(0.125f * qp[(long)(rrow + 8) * LDQ + c0 + 4]);
    }

    uint32_t* Psw = Ksm + warp * 16 * 36;   // warp-private 16x36 P slice

    float m0 = -INFINITY, m1 = -INFINITY, l0 = 0.f, l1 = 0.f;
    float oacc[8][4];
#pragma unroll
    for (int nf = 0; nf < 8; nf++)
#pragma unroll
        for (int c = 0; c < 4; c++) oacc[nf][c] = 0.f;

    for (int t = 0; t < SS / 64; t++) {
        int k0 = t * 64;
        __syncthreads();   // prior-iter P/V smem reads done before overwrite
        {
            int r = tid >> 4, c = (tid & 15) * 4;
#pragma unroll
            for (int i = 0; i < 4; i++) {
                int row = r + 16 * i;
                float4 k4 = *(const float4*)(kp + (long)(k0 + row) * LDQ + c);
                *(uint4*)&Ksm[row * KS + c] = cvt4(k4);
                float4 v4 = *(const float4*)(vp + (long)(k0 + row) * LDQ + c);
                *(uint4*)&Vsm[row * VS + c] = cvt4(v4);
            }
            if (tid < 64) mAdd[tid] = (mp[k0 + tid] == 0) ? NEGV : 0.f;
        }
        __syncthreads();

        // S = (Q/8) @ K^T : 16x64 per warp
        float sacc[8][4];
#pragma unroll
        for (int nf = 0; nf < 8; nf++)
#pragma unroll
            for (int c = 0; c < 4; c++) sacc[nf][c] = 0.f;
#pragma unroll
        for (int ks = 0; ks < 8; ks++) {
#pragma unroll
            for (int nf = 0; nf < 8; nf++) {
                int c = nf * 8 + g;
                uint32_t b0 = Ksm[c * KS + ks * 8 + tg];
                uint32_t b1 = Ksm[c * KS + ks * 8 + tg + 4];
                mma_tf32(sacc[nf], qf[ks][0], qf[ks][1], qf[ks][2], qf[ks][3], b0, b1);
            }
        }
        __syncthreads();   // ALL warps' K reads done before P staging reuses Ksm

        // mask + tile rowmax
        float tm0 = -INFINITY, tm1 = -INFINITY;
#pragma unroll
        for (int nf = 0; nf < 8; nf++) {
            float2 ma = *(const float2*)&mAdd[nf * 8 + 2 * tg];
            sacc[nf][0] += ma.x; sacc[nf][1] += ma.y;
            sacc[nf][2] += ma.x; sacc[nf][3] += ma.y;
            tm0 = fmaxf(tm0, fmaxf(sacc[nf][0], sacc[nf][1]));
            tm1 = fmaxf(tm1, fmaxf(sacc[nf][2], sacc[nf][3]));
        }
#pragma unroll
        for (int o = 1; o <= 2; o <<= 1) {
            tm0 = fmaxf(tm0, __shfl_xor_sync(0xffffffffu, tm0, o));
            tm1 = fmaxf(tm1, __shfl_xor_sync(0xffffffffu, tm1, o));
        }
        float nm0 = fmaxf(m0, tm0), nm1 = fmaxf(m1, tm1);
        float r0 = __expf(m0 - nm0), r1 = __expf(m1 - nm1);

        float s0 = 0.f, s1 = 0.f;
#pragma unroll
        for (int nf = 0; nf < 8; nf++) {
            sacc[nf][0] = __expf(sacc[nf][0] - nm0);
            sacc[nf][1] = __expf(sacc[nf][1] - nm0);
            sacc[nf][2] = __expf(sacc[nf][2] - nm1);
            sacc[nf][3] = __expf(sacc[nf][3] - nm1);
            s0 += sacc[nf][0] + sacc[nf][1];
            s1 += sacc[nf][2] + sacc[nf][3];
        }
#pragma unroll
        for (int o = 1; o <= 2; o <<= 1) {
            s0 += __shfl_xor_sync(0xffffffffu, s0, o);
            s1 += __shfl_xor_sync(0xffffffffu, s1, o);
        }
        l0 = l0 * r0 + s0; l1 = l1 * r1 + s1;
        m0 = nm0; m1 = nm1;
#pragma unroll
        for (int nf = 0; nf < 8; nf++) {
            oacc[nf][0] *= r0; oacc[nf][1] *= r0;
            oacc[nf][2] *= r1; oacc[nf][3] *= r1;
        }

        // O += P @ V in two 32-key halves (P chunk 16x32 fits stride 36)
#pragma unroll
        for (int half = 0; half < 2; half++) {
            __syncwarp();
#pragma unroll
            for (int nf4 = 0; nf4 < 4; nf4++) {
                int nf = half * 4 + nf4;
                *(uint2*)&Psw[g * 36 + nf4 * 8 + 2 * tg] =
                    make_uint2(f2tf(sacc[nf][0]), f2tf(sacc[nf][1]));
                *(uint2*)&Psw[(g + 8) * 36 + nf4 * 8 + 2 * tg] =
                    make_uint2(f2tf(sacc[nf][2]), f2tf(sacc[nf][3]));
            }
            __syncwarp();
#pragma unroll
            for (int ks4 = 0; ks4 < 4; ks4++) {
                int ks = half * 4 + ks4;
                uint32_t a0 = Psw[g * 36 + ks4 * 8 + tg];
                uint32_t a1 = Psw[(g + 8) * 36 + ks4 * 8 + tg];
                uint32_t a2 = Psw[g * 36 + ks4 * 8 + tg + 4];
                uint32_t a3 = Psw[(g + 8) * 36 + ks4 * 8 + tg + 4];
#pragma unroll
                for (int nf = 0; nf < 8; nf++) {
                    uint32_t b0 = Vsm[(ks * 8 + tg) * VS + nf * 8 + g];
                    uint32_t b1 = Vsm[(ks * 8 + tg + 4) * VS + nf * 8 + g];
                    mma_tf32(oacc[nf], a0, a1, a2, a3, b0, b1);
                }
            }
        }
    }

    // epilogue: out[token][h*64 + d]
    float i0 = 1.f / l0, i1 = 1.f / l1;
    float* op = out + (long)b * SS * DM + h * HD;
#pragma unroll
    for (int nf = 0; nf < 8; nf++) {
        int c = nf * 8 + 2 * tg;
        float2 v0 = make_float2(oacc[nf][0] * i0, oacc[nf][1] * i0);
        float2 v1 = make_float2(oacc[nf][2] * i1, oacc[nf][3] * i1);
        *(float2*)(op + (long)rrow * DM + c) = v0;
        *(float2*)(op + (long)(rrow + 8) * DM + c) = v1;
    }
}

// ---------------------------------------------------------------------------
// TF32 tensor-core GEMM (validated in R2).
// ---------------------------------------------------------------------------
template <int BM, int BN, bool TRANSB, bool RELU, bool BIAS, bool RES>
__global__ __launch_bounds__(256) void mma_gemm(
    const float* __restrict__ A, const float* __restrict__ Bm,
    const float* __restrict__ bias, const float* __restrict__ res,
    float* __restrict__ C,
    int M, int N, int K, int lda, int ldb, int ldc,
    float alpha) {
    constexpr int BK = 32;
    constexpr int AS = 36;
    constexpr int BSN = BN + 8;
    constexpr int WARPS_N = BN / 32;
    constexpr int WARPS_M = 8 / WARPS_N;
    constexpr int WM = BM / WARPS_M;
    constexpr int MT = WM / 16;
    constexpr int NT = 4;

    __shared__ uint32_t Asm[BM * AS];
    __shared__ uint32_t Bsm[TRANSB ? (BN * AS) : (BK * BSN)];

    int bm = blockIdx.y * BM;
    int bn = blockIdx.x * BN;
    int tid  = threadIdx.x;
    int warp = tid >> 5;
    int lane = tid & 31;
    int g  = lane >> 2;
    int tg = lane & 3;
    int wm = warp / WARPS_N;
    int wn = warp % WARPS_N;

    float acc[MT][NT][4];
#pragma unroll
    for (int i = 0; i < MT; i++)
#pragma unroll
        for (int j = 0; j < NT; j++)
#pragma unroll
            for (int c = 0; c < 4; c++) acc[i][j][c] = 0.f;

    const int am = tid >> 3;
    const int ak = (tid & 7) * 4;
    constexpr int AITERS = BM / 32;

    constexpr int BCOLS = BN / 4;
    constexpr int BROWS = 256 / BCOLS;
    constexpr int BITERS_N = BK / BROWS;
    constexpr int BITERS_T = BN / 32;
    constexpr int BITERS = TRANSB ? BITERS_T : BITERS_N;
    const int bk_ = tid / BCOLS;
    const int bn_ = (tid % BCOLS) * 4;

    float4 aR[AITERS];
    float4 bR[BITERS];

    const int nTiles = K / BK;

#pragma unroll
    for (int i = 0; i < AITERS; i++)
        aR[i] = *(const float4*)(A + (long)(bm + am + 32 * i) * lda + ak);
    if (TRANSB) {
#pragma unroll
        for (int i = 0; i < BITERS; i++)
            bR[i] = *(const float4*)(Bm + (long)(bn + am + 32 * i) * ldb + ak);
    } else {
#pragma unroll
        for (int i = 0; i < BITERS; i++)
            bR[i] = *(const float4*)(Bm + (long)(bk_ + BROWS * i) * ldb + bn + bn_);
    }
#pragma unroll
    for (int i = 0; i < AITERS; i++)
        *(uint4*)&Asm[(am + 32 * i) * AS + ak] = cvt4(aR[i]);
    if (TRANSB) {
#pragma unroll
        for (int i = 0; i < BITERS; i++)
            *(uint4*)&Bsm[(am + 32 * i) * AS + ak] = cvt4(bR[i]);
    } else {
#pragma unroll
        for (int i = 0; i < BITERS; i++)
            *(uint4*)&Bsm[(bk_ + BROWS * i) * BSN + bn_] = cvt4(bR[i]);
    }
    __syncthreads();

    for (int t = 0; t < nTiles; t++) {
        int k0n = (t + 1) * BK;
        if (t + 1 < nTiles) {
#pragma unroll
            for (int i = 0; i < AITERS; i++)
                aR[i] = *(const float4*)(A + (long)(bm + am + 32 * i) * lda + k0n + ak);
            if (TRANSB) {
#pragma unroll
                for (int i = 0; i < BITERS; i++)
                    bR[i] = *(const float4*)(Bm + (long)(bn + am + 32 * i) * ldb + k0n + ak);
            } else {
#pragma unroll
                for (int i = 0; i < BITERS; i++)
                    bR[i] = *(const float4*)(Bm + (long)(k0n + bk_ + BROWS * i) * ldb + bn + bn_);
            }
        }

#pragma unroll
        for (int ks = 0; ks < 4; ks++) {
            uint32_t af[MT][4];
            uint32_t bf[NT][2];
#pragma unroll
            for (int mt = 0; mt < MT; mt++) {
                int r = wm * WM + mt * 16 + g;
                af[mt][0] = Asm[r * AS + ks * 8 + tg];
                af[mt][1] = Asm[(r + 8) * AS + ks * 8 + tg];
                af[mt][2] = Asm[r * AS + ks * 8 + tg + 4];
                af[mt][3] = Asm[(r + 8) * AS + ks * 8 + tg + 4];
            }
#pragma unroll
            for (int nt = 0; nt < NT; nt++) {
                int c = wn * 32 + nt * 8 + g;
                if (TRANSB) {
                    bf[nt][0] = Bsm[c * AS + ks * 8 + tg];
                    bf[nt][1] = Bsm[c * AS + ks * 8 + tg + 4];
                } else {
                    bf[nt][0] = Bsm[(ks * 8 + tg) * BSN + c];
                    bf[nt][1] = Bsm[(ks * 8 + tg + 4) * BSN + c];
                }
            }
#pragma unroll
            for (int mt = 0; mt < MT; mt++)
#pragma unroll
                for (int nt = 0; nt < NT; nt++)
                    mma_tf32(acc[mt][nt], af[mt][0], af[mt][1], af[mt][2], af[mt][3],
                             bf[nt][0], bf[nt][1]);
        }
        __syncthreads();

        if (t + 1 < nTiles) {
#pragma unroll
            for (int i = 0; i < AITERS; i++)
                *(uint4*)&Asm[(am + 32 * i) * AS + ak] = cvt4(aR[i]);
            if (TRANSB) {
#pragma unroll
                for (int i = 0; i < BITERS; i++)
                    *(uint4*)&Bsm[(am + 32 * i) * AS + ak] = cvt4(bR[i]);
            } else {
#pragma unroll
                for (int i = 0; i < BITERS; i++)
                    *(uint4*)&Bsm[(bk_ + BROWS * i) * BSN + bn_] = cvt4(bR[i]);
            }
            __syncthreads();
        }
    }

#pragma unroll
    for (int mt = 0; mt < MT; mt++) {
        int r = bm + wm * WM + mt * 16 + g;
#pragma unroll
        for (int nt = 0; nt < NT; nt++) {
            int c = bn + wn * 32 + nt * 8 + tg * 2;
            float2 v0, v1;
            v0.x = acc[mt][nt][0] * alpha; v0.y = acc[mt][nt][1] * alpha;
            v1.x = acc[mt][nt][2] * alpha; v1.y = acc[mt][nt][3] * alpha;
            if (BIAS) {
                float2 bv = *(const float2*)(bias + c);
                v0.x += bv.x; v0.y += bv.y; v1.x += bv.x; v1.y += bv.y;
            }
            if (RELU) {
                v0.x = fmaxf(v0.x, 0.f); v0.y = fmaxf(v0.y, 0.f);
                v1.x = fmaxf(v1.x, 0.f); v1.y = fmaxf(v1.y, 0.f);
            }
            if (RES) {
                float2 r0 = *(const float2*)(res + (long)r * ldc + c);
                float2 r1 = *(const float2*)(res + (long)(r + 8) * ldc + c);
                v0.x += r0.x; v0.y += r0.y; v1.x += r1.x; v1.y += r1.y;
            }
            *(float2*)(C + (long)r * ldc + c) = v0;
            *(float2*)(C + (long)(r + 8) * ldc + c) = v1;
        }
    }
}

// ---------------------------------------------------------------------------
// Host side
// ---------------------------------------------------------------------------
template <typename T>
static float* sym(const T& s) {
    void* p = nullptr;
    cudaGetSymbolAddress(&p, s);
    return (float*)p;
}

extern "C" void kernel_launch(void* const* d_in, const int* in_sizes, int n_in,
                              void* d_out, int out_size) {
    const float* x      = (const float*)d_in[0];
    const int*   mask   = (const int*)d_in[1];
    const float* Wq     = (const float*)d_in[2];
    const float* bq     = (const float*)d_in[3];
    const float* Wk     = (const float*)d_in[4];
    const float* bk     = (const float*)d_in[5];
    const float* Wv     = (const float*)d_in[6];
    const float* bv     = (const float*)d_in[7];
    const float* Wo     = (const float*)d_in[8];
    const float* bo     = (const float*)d_in[9];
    const float* W1     = (const float*)d_in[10];
    const float* b1     = (const float*)d_in[11];
    const float* W2     = (const float*)d_in[12];
    const float* b2     = (const float*)d_in[13];
    const float* alpha1 = (const float*)d_in[14];
    const float* beta1  = (const float*)d_in[15];
    const float* alpha2 = (const float*)d_in[16];
    const float* beta2  = (const float*)d_in[17];
    float* out = (float*)d_out;

    float* n1   = sym(g_n1);
    float* qkv  = sym(g_qkv);
    float* wcat = sym(g_wcat);
    float* bcat = sym(g_bcat);
    float* attn = sym(g_attn);
    float* h    = sym(g_h);
    float* n2   = sym(g_n2);
    float* ffn  = sym(g_ffn);

    // 0. concat QKV weights
    concat_w<<<(DM * 3 * DM) / 256, 256>>>(Wq, Wk, Wv, bq, bk, bv, wcat, bcat);

    // 1. LN1
    ln_kernel<<<NTOK, 256>>>(x, alpha1, beta1, n1);

    // 2. fused QKV projection: [4096,1024] @ [1024,3072] + bias
    {
        dim3 grid(3 * DM / 128, NTOK / 128, 1);
        mma_gemm<128, 128, false, false, true, false><<<grid, 256>>>(
            n1, wcat, bcat, nullptr, qkv, NTOK, 3 * DM, DM, DM, 3 * DM, 3 * DM, 1.0f);
    }

    // 3-5. flash attention (scores + mask + softmax + PV fused)
    {
        dim3 grid(SS / 128, HH, BB);
        flash_kernel<<<grid, 256>>>(qkv, mask, attn);
    }

    // 6. h = x + attn @ Wo + bo
    {
        dim3 grid(DM / 128, NTOK / 128, 1);
        mma_gemm<128, 128, false, false, true, true><<<grid, 256>>>(
            attn, Wo, bo, x, h, NTOK, DM, DM, DM, DM, DM, 1.0f);
    }

    // 7. LN2
    ln_kernel<<<NTOK, 256>>>(h, alpha2, beta2, n2);

    // 8. ffn = relu(n2 @ W1 + b1)
    {
        dim3 grid(DF / 128, NTOK / 128, 1);
        mma_gemm<128, 128, false, true, true, false><<<grid, 256>>>(
            n2, W1, b1, nullptr, ffn, NTOK, DF, DM, DM, DF, DF, 1.0f);
    }

    // 9. out = h + ffn @ W2 + b2
    {
        dim3 grid(DM / 128, NTOK / 128, 1);
        mma_gemm<128, 128, false, false, true, true><<<grid, 256>>>(
            ffn, W2, b2, h, out, NTOK, DM, DF, DF, DM, DM, 1.0f);
    }
}

// round 8
// speedup vs baseline: 4.7664x; 1.1352x over previous
#include <cuda_runtime.h>
#include <cuda_bf16.h>
#include <math.h>
#include <stdint.h>

// Problem constants
#define BB 2
#define SS 2048
#define DM 1024
#define HH 16
#define HD 64
#define DF 4096
#define NTOK (BB * SS)          // 4096
#define NEGV (-1e9f)
#define EPS 1e-6f

// ---------------------------------------------------------------------------
// Scratch (device globals — no allocation allowed)
// ---------------------------------------------------------------------------
__device__ float g_n1[NTOK * DM];
__device__ float g_qkv[(long)NTOK * 3 * DM];   // q|k|v interleaved per row
__device__ float g_wcat[DM * 3 * DM];          // Wq|Wk|Wv  [1024][3072]
__device__ float g_bcat[3 * DM];
__device__ float g_attn[NTOK * DM];
__device__ float g_h[NTOK * DM];
__device__ float g_n2[NTOK * DM];
__device__ float g_ffn[(long)NTOK * DF];

// ---------------------------------------------------------------------------
// Helpers
// ---------------------------------------------------------------------------
__device__ __forceinline__ uint32_t f2tf(float f) {
    uint32_t u;
    asm("cvt.rna.tf32.f32 %0, %1;" : "=r"(u) : "f"(f));
    return u;
}
__device__ __forceinline__ uint4 cvt4(float4 v) {
    uint4 r;
    r.x = f2tf(v.x); r.y = f2tf(v.y); r.z = f2tf(v.z); r.w = f2tf(v.w);
    return r;
}
__device__ __forceinline__ void mma_tf32(float c[4], uint32_t a0, uint32_t a1,
                                         uint32_t a2, uint32_t a3,
                                         uint32_t b0, uint32_t b1) {
    asm volatile(
        "mma.sync.aligned.m16n8k8.row.col.f32.tf32.tf32.f32 "
        "{%0,%1,%2,%3}, {%4,%5,%6,%7}, {%8,%9}, {%0,%1,%2,%3};"
        : "+f"(c[0]), "+f"(c[1]), "+f"(c[2]), "+f"(c[3])
        : "r"(a0), "r"(a1), "r"(a2), "r"(a3), "r"(b0), "r"(b1));
}
__device__ __forceinline__ void cpa16(float* dst, const float* src) {
    uint32_t d = (uint32_t)__cvta_generic_to_shared(dst);
    asm volatile("cp.async.cg.shared.global [%0], [%1], 16;" :: "r"(d), "l"(src));
}
__device__ __forceinline__ void cpa_commit() {
    asm volatile("cp.async.commit_group;" ::: "memory");
}
__device__ __forceinline__ void cpa_wait1() {
    asm volatile("cp.async.wait_group 1;" ::: "memory");
}

// ---------------------------------------------------------------------------
// Concat Wq|Wk|Wv and biases into contiguous [1024][3072] / [3072]
// ---------------------------------------------------------------------------
__global__ __launch_bounds__(256) void concat_w(
    const float* __restrict__ Wq, const float* __restrict__ Wk,
    const float* __restrict__ Wv, const float* __restrict__ bq,
    const float* __restrict__ bk, const float* __restrict__ bv,
    float* __restrict__ wcat, float* __restrict__ bcat) {
    long i = blockIdx.x * 256L + threadIdx.x;
    int row = (int)(i / (3 * DM));
    int col = (int)(i % (3 * DM));
    const float* W = (col < DM) ? Wq : ((col < 2 * DM) ? Wk : Wv);
    wcat[i] = W[row * DM + (col & (DM - 1))];
    if (i < 3 * DM) {
        const float* bb = (i < DM) ? bq : ((i < 2 * DM) ? bk : bv);
        bcat[i] = bb[i & (DM - 1)];
    }
}

// ---------------------------------------------------------------------------
// LayerNorm (torch semantics: unbiased std (ddof=1), eps added to std)
// ---------------------------------------------------------------------------
__global__ __launch_bounds__(256) void ln_kernel(const float* __restrict__ x,
                                                 const float* __restrict__ alpha,
                                                 const float* __restrict__ beta,
                                                 float* __restrict__ out) {
    long row = blockIdx.x;
    const float4* xr = (const float4*)(x + row * DM);
    float4 v = xr[threadIdx.x];

    float s  = v.x + v.y + v.z + v.w;
    float ss = v.x * v.x + v.y * v.y + v.z * v.z + v.w * v.w;

    __shared__ float sa[8], sb[8];
#pragma unroll
    for (int o = 16; o > 0; o >>= 1) {
        s  += __shfl_xor_sync(0xffffffffu, s, o);
        ss += __shfl_xor_sync(0xffffffffu, ss, o);
    }
    if ((threadIdx.x & 31) == 0) { sa[threadIdx.x >> 5] = s; sb[threadIdx.x >> 5] = ss; }
    __syncthreads();
    s = 0.f; ss = 0.f;
#pragma unroll
    for (int i = 0; i < 8; i++) { s += sa[i]; ss += sb[i]; }

    float mean = s * (1.0f / DM);
    float var  = (ss - (float)DM * mean * mean) * (1.0f / (DM - 1));
    var = fmaxf(var, 0.0f);
    float inv  = alpha[0] / (sqrtf(var) + EPS);
    float bta  = beta[0];

    float4 o;
    o.x = (v.x - mean) * inv + bta;
    o.y = (v.y - mean) * inv + bta;
    o.z = (v.z - mean) * inv + bta;
    o.w = (v.w - mean) * inv + bta;
    ((float4*)(out + row * DM))[threadIdx.x] = o;
}

// ---------------------------------------------------------------------------
// Flash attention (TF32 tensor cores, online softmax) — unchanged from R7.
// ---------------------------------------------------------------------------
__global__ __launch_bounds__(256) void flash_kernel(
    const float* __restrict__ qkv, const int* __restrict__ mask,
    float* __restrict__ out) {
    constexpr int LDQ = 3 * DM;
    constexpr int KS = 76;
    constexpr int VS = 72;
    int qb = blockIdx.x * 128;
    int h  = blockIdx.y;
    int b  = blockIdx.z;
    const float* qp = qkv + (long)b * SS * LDQ + h * HD;
    const float* kp = qp + DM;
    const float* vp = qp + 2 * DM;
    const int* mp = mask + b * SS;

    __shared__ uint32_t Ksm[64 * KS];   // K tile / P staging
    __shared__ uint32_t Vsm[64 * VS];
    __shared__ float mAdd[64];

    int tid = threadIdx.x, warp = tid >> 5, lane = tid & 31;
    int g = lane >> 2, tg = lane & 3;
    int rrow = qb + warp * 16 + g;

    // Q fragments straight from gmem (scaled by 1/sqrt(HD)=0.125, tf32)
    uint32_t qf[8][4];
#pragma unroll
    for (int ks = 0; ks < 8; ks++) {
        int c0 = ks * 8 + tg;
        qf[ks][0] = f2tf(0.125f * qp[(long)rrow * LDQ + c0]);
        qf[ks][1] = f2tf(0.125f * qp[(long)(rrow + 8) * LDQ + c0]);
        qf[ks][2] = f2tf(0.125f * qp[(long)rrow * LDQ + c0 + 4]);
        qf[ks][3] = f2tf(0.125f * qp[(long)(rrow + 8) * LDQ + c0 + 4]);
    }

    uint32_t* Psw = Ksm + warp * 16 * 36;   // warp-private 16x36 P slice

    float m0 = -INFINITY, m1 = -INFINITY, l0 = 0.f, l1 = 0.f;
    float oacc[8][4];
#pragma unroll
    for (int nf = 0; nf < 8; nf++)
#pragma unroll
        for (int c = 0; c < 4; c++) oacc[nf][c] = 0.f;

    for (int t = 0; t < SS / 64; t++) {
        int k0 = t * 64;
        __syncthreads();   // prior-iter P/V smem reads done before overwrite
        {
            int r = tid >> 4, c = (tid & 15) * 4;
#pragma unroll
            for (int i = 0; i < 4; i++) {
                int row = r + 16 * i;
                float4 k4 = *(const float4*)(kp + (long)(k0 + row) * LDQ + c);
                *(uint4*)&Ksm[row * KS + c] = cvt4(k4);
                float4 v4 = *(const float4*)(vp + (long)(k0 + row) * LDQ + c);
                *(uint4*)&Vsm[row * VS + c] = cvt4(v4);
            }
            if (tid < 64) mAdd[tid] = (mp[k0 + tid] == 0) ? NEGV : 0.f;
        }
        __syncthreads();

        // S = (Q/8) @ K^T : 16x64 per warp
        float sacc[8][4];
#pragma unroll
        for (int nf = 0; nf < 8; nf++)
#pragma unroll
            for (int c = 0; c < 4; c++) sacc[nf][c] = 0.f;
#pragma unroll
        for (int ks = 0; ks < 8; ks++) {
#pragma unroll
            for (int nf = 0; nf < 8; nf++) {
                int c = nf * 8 + g;
                uint32_t b0 = Ksm[c * KS + ks * 8 + tg];
                uint32_t b1 = Ksm[c * KS + ks * 8 + tg + 4];
                mma_tf32(sacc[nf], qf[ks][0], qf[ks][1], qf[ks][2], qf[ks][3], b0, b1);
            }
        }
        __syncthreads();   // ALL warps' K reads done before P staging reuses Ksm

        // mask + tile rowmax
        float tm0 = -INFINITY, tm1 = -INFINITY;
#pragma unroll
        for (int nf = 0; nf < 8; nf++) {
            float2 ma = *(const float2*)&mAdd[nf * 8 + 2 * tg];
            sacc[nf][0] += ma.x; sacc[nf][1] += ma.y;
            sacc[nf][2] += ma.x; sacc[nf][3] += ma.y;
            tm0 = fmaxf(tm0, fmaxf(sacc[nf][0], sacc[nf][1]));
            tm1 = fmaxf(tm1, fmaxf(sacc[nf][2], sacc[nf][3]));
        }
#pragma unroll
        for (int o = 1; o <= 2; o <<= 1) {
            tm0 = fmaxf(tm0, __shfl_xor_sync(0xffffffffu, tm0, o));
            tm1 = fmaxf(tm1, __shfl_xor_sync(0xffffffffu, tm1, o));
        }
        float nm0 = fmaxf(m0, tm0), nm1 = fmaxf(m1, tm1);
        float r0 = __expf(m0 - nm0), r1 = __expf(m1 - nm1);

        float s0 = 0.f, s1 = 0.f;
#pragma unroll
        for (int nf = 0; nf < 8; nf++) {
            sacc[nf][0] = __expf(sacc[nf][0] - nm0);
            sacc[nf][1] = __expf(sacc[nf][1] - nm0);
            sacc[nf][2] = __expf(sacc[nf][2] - nm1);
            sacc[nf][3] = __expf(sacc[nf][3] - nm1);
            s0 += sacc[nf][0] + sacc[nf][1];
            s1 += sacc[nf][2] + sacc[nf][3];
        }
#pragma unroll
        for (int o = 1; o <= 2; o <<= 1) {
            s0 += __shfl_xor_sync(0xffffffffu, s0, o);
            s1 += __shfl_xor_sync(0xffffffffu, s1, o);
        }
        l0 = l0 * r0 + s0; l1 = l1 * r1 + s1;
        m0 = nm0; m1 = nm1;
#pragma unroll
        for (int nf = 0; nf < 8; nf++) {
            oacc[nf][0] *= r0; oacc[nf][1] *= r0;
            oacc[nf][2] *= r1; oacc[nf][3] *= r1;
        }

        // O += P @ V in two 32-key halves (P chunk 16x32 fits stride 36)
#pragma unroll
        for (int half = 0; half < 2; half++) {
            __syncwarp();
#pragma unroll
            for (int nf4 = 0; nf4 < 4; nf4++) {
                int nf = half * 4 + nf4;
                *(uint2*)&Psw[g * 36 + nf4 * 8 + 2 * tg] =
                    make_uint2(f2tf(sacc[nf][0]), f2tf(sacc[nf][1]));
                *(uint2*)&Psw[(g + 8) * 36 + nf4 * 8 + 2 * tg] =
                    make_uint2(f2tf(sacc[nf][2]), f2tf(sacc[nf][3]));
            }
            __syncwarp();
#pragma unroll
            for (int ks4 = 0; ks4 < 4; ks4++) {
                int ks = half * 4 + ks4;
                uint32_t a0 = Psw[g * 36 + ks4 * 8 + tg];
                uint32_t a1 = Psw[(g + 8) * 36 + ks4 * 8 + tg];
                uint32_t a2 = Psw[g * 36 + ks4 * 8 + tg + 4];
                uint32_t a3 = Psw[(g + 8) * 36 + ks4 * 8 + tg + 4];
#pragma unroll
                for (int nf = 0; nf < 8; nf++) {
                    uint32_t b0 = Vsm[(ks * 8 + tg) * VS + nf * 8 + g];
                    uint32_t b1 = Vsm[(ks * 8 + tg + 4) * VS + nf * 8 + g];
                    mma_tf32(oacc[nf], a0, a1, a2, a3, b0, b1);
                }
            }
        }
    }

    // epilogue: out[token][h*64 + d]
    float i0 = 1.f / l0, i1 = 1.f / l1;
    float* op = out + (long)b * SS * DM + h * HD;
#pragma unroll
    for (int nf = 0; nf < 8; nf++) {
        int c = nf * 8 + 2 * tg;
        float2 v0 = make_float2(oacc[nf][0] * i0, oacc[nf][1] * i0);
        float2 v1 = make_float2(oacc[nf][2] * i1, oacc[nf][3] * i1);
        *(float2*)(op + (long)rrow * DM + c) = v0;
        *(float2*)(op + (long)(rrow + 8) * DM + c) = v1;
    }
}

// ---------------------------------------------------------------------------
// TF32 GEMM v2: cp.async 3-stage pipeline, one __syncthreads per K-tile.
// C[m,n] = sum_k A[m,k]*B[k,n] (+bias) (relu) (+res).  BM=128, BN=128, BK=32.
// 256 threads = 8 warps (2x4), warp tile 64x32, MT=4, NT=4.
// Smem holds raw fp32 (cp.async can't convert); cvt.rna.tf32 at fragment load
// (identical numerics to converting at store).
// Smem ring: 3 stages x (A 128x36 + B 32x136) fp32 = 107,520 B (dynamic).
// Per iter t: wait_group 1 (tile t landed) -> sync -> cp.async tile t+2 into
// slot (t+2)%3 (== slot of t-1, which all warps finished before the sync) ->
// commit -> compute tile t.  Tiles t+1, t+2 stay in flight during compute.
// ---------------------------------------------------------------------------
template <bool RELU, bool BIAS, bool RES>
__global__ __launch_bounds__(256) void mma_gemm2(
    const float* __restrict__ A, const float* __restrict__ Bm,
    const float* __restrict__ bias, const float* __restrict__ res,
    float* __restrict__ C, int K, int lda, int ldb, int ldc) {
    constexpr int BK = 32, AS = 36, BS = 136;
    constexpr int ASTG = 128 * AS;   // 4608 floats
    constexpr int BSTG = BK * BS;    // 4352 floats

    extern __shared__ float smem[];
    float* Asm = smem;
    float* Bsm = smem + 3 * ASTG;

    int bm = blockIdx.y * 128;
    int bn = blockIdx.x * 128;
    int tid = threadIdx.x, warp = tid >> 5, lane = tid & 31;
    int g = lane >> 2, tg = lane & 3;
    int wm = warp >> 2, wn = warp & 3;

    const int am = tid >> 3;             // 0..31
    const int ak = (tid & 7) * 4;        // 0..28
    const int bk_ = tid >> 5;            // 0..7
    const int bn_ = (tid & 31) * 4;      // 0..124
    const int nT = K / BK;

    const float* Agp = A + (long)(bm + am) * lda + ak;
    const float* Bgp = Bm + (long)bk_ * ldb + bn + bn_;
    float* Aw = Asm + am * AS + ak;
    float* Bw = Bsm + bk_ * BS + bn_;

    // prologue: tiles 0 and 1
#pragma unroll
    for (int p = 0; p < 2; p++) {
        int slot = p;
#pragma unroll
        for (int i = 0; i < 4; i++)
            cpa16(Aw + slot * ASTG + 32 * i * AS, Agp + (long)32 * i * lda + p * BK);
#pragma unroll
        for (int i = 0; i < 4; i++)
            cpa16(Bw + slot * BSTG + 8 * i * BS, Bgp + (long)(p * BK + 8 * i) * ldb);
        cpa_commit();
    }

    float acc[4][4][4];
#pragma unroll
    for (int i = 0; i < 4; i++)
#pragma unroll
        for (int j = 0; j < 4; j++)
#pragma unroll
            for (int c = 0; c < 4; c++) acc[i][j][c] = 0.f;

    for (int t = 0; t < nT; t++) {
        cpa_wait1();
        __syncthreads();

        if (t + 2 < nT) {
            int slot = (t + 2) % 3;
            int k0 = (t + 2) * BK;
#pragma unroll
            for (int i = 0; i < 4; i++)
                cpa16(Aw + slot * ASTG + 32 * i * AS, Agp + (long)32 * i * lda + k0);
#pragma unroll
            for (int i = 0; i < 4; i++)
                cpa16(Bw + slot * BSTG + 8 * i * BS, Bgp + (long)(k0 + 8 * i) * ldb);
        }
        cpa_commit();

        const float* As = Asm + (t % 3) * ASTG;
        const float* Bs = Bsm + (t % 3) * BSTG;

#pragma unroll
        for (int ks = 0; ks < 4; ks++) {
            uint32_t af[4][4];
            uint32_t bf[4][2];
#pragma unroll
            for (int mt = 0; mt < 4; mt++) {
                int r = wm * 64 + mt * 16 + g;
                af[mt][0] = f2tf(As[r * AS + ks * 8 + tg]);
                af[mt][1] = f2tf(As[(r + 8) * AS + ks * 8 + tg]);
                af[mt][2] = f2tf(As[r * AS + ks * 8 + tg + 4]);
                af[mt][3] = f2tf(As[(r + 8) * AS + ks * 8 + tg + 4]);
            }
#pragma unroll
            for (int nt = 0; nt < 4; nt++) {
                int c = wn * 32 + nt * 8 + g;
                bf[nt][0] = f2tf(Bs[(ks * 8 + tg) * BS + c]);
                bf[nt][1] = f2tf(Bs[(ks * 8 + tg + 4) * BS + c]);
            }
#pragma unroll
            for (int mt = 0; mt < 4; mt++)
#pragma unroll
                for (int nt = 0; nt < 4; nt++)
                    mma_tf32(acc[mt][nt], af[mt][0], af[mt][1], af[mt][2], af[mt][3],
                             bf[nt][0], bf[nt][1]);
        }
    }

    // epilogue
#pragma unroll
    for (int mt = 0; mt < 4; mt++) {
        int r = bm + wm * 64 + mt * 16 + g;
#pragma unroll
        for (int nt = 0; nt < 4; nt++) {
            int c = bn + wn * 32 + nt * 8 + tg * 2;
            float2 v0, v1;
            v0.x = acc[mt][nt][0]; v0.y = acc[mt][nt][1];
            v1.x = acc[mt][nt][2]; v1.y = acc[mt][nt][3];
            if (BIAS) {
                float2 bv = *(const float2*)(bias + c);
                v0.x += bv.x; v0.y += bv.y; v1.x += bv.x; v1.y += bv.y;
            }
            if (RELU) {
                v0.x = fmaxf(v0.x, 0.f); v0.y = fmaxf(v0.y, 0.f);
                v1.x = fmaxf(v1.x, 0.f); v1.y = fmaxf(v1.y, 0.f);
            }
            if (RES) {
                float2 r0 = *(const float2*)(res + (long)r * ldc + c);
                float2 r1 = *(const float2*)(res + (long)(r + 8) * ldc + c);
                v0.x += r0.x; v0.y += r0.y; v1.x += r1.x; v1.y += r1.y;
            }
            *(float2*)(C + (long)r * ldc + c) = v0;
            *(float2*)(C + (long)(r + 8) * ldc + c) = v1;
        }
    }
}

// ---------------------------------------------------------------------------
// Host side
// ---------------------------------------------------------------------------
template <typename T>
static float* sym(const T& s) {
    void* p = nullptr;
    cudaGetSymbolAddress(&p, s);
    return (float*)p;
}

#define GEMM_SMEM 107520

extern "C" void kernel_launch(void* const* d_in, const int* in_sizes, int n_in,
                              void* d_out, int out_size) {
    const float* x      = (const float*)d_in[0];
    const int*   mask   = (const int*)d_in[1];
    const float* Wq     = (const float*)d_in[2];
    const float* bq     = (const float*)d_in[3];
    const float* Wk     = (const float*)d_in[4];
    const float* bk     = (const float*)d_in[5];
    const float* Wv     = (const float*)d_in[6];
    const float* bv     = (const float*)d_in[7];
    const float* Wo     = (const float*)d_in[8];
    const float* bo     = (const float*)d_in[9];
    const float* W1     = (const float*)d_in[10];
    const float* b1     = (const float*)d_in[11];
    const float* W2     = (const float*)d_in[12];
    const float* b2     = (const float*)d_in[13];
    const float* alpha1 = (const float*)d_in[14];
    const float* beta1  = (const float*)d_in[15];
    const float* alpha2 = (const float*)d_in[16];
    const float* beta2  = (const float*)d_in[17];
    float* out = (float*)d_out;

    float* n1   = sym(g_n1);
    float* qkv  = sym(g_qkv);
    float* wcat = sym(g_wcat);
    float* bcat = sym(g_bcat);
    float* attn = sym(g_attn);
    float* h    = sym(g_h);
    float* n2   = sym(g_n2);
    float* ffn  = sym(g_ffn);

    // opt-in to >48KB dynamic smem for all GEMM instantiations (idempotent)
    cudaFuncSetAttribute(mma_gemm2<false, true, false>,
                         cudaFuncAttributeMaxDynamicSharedMemorySize, GEMM_SMEM);
    cudaFuncSetAttribute(mma_gemm2<false, true, true>,
                         cudaFuncAttributeMaxDynamicSharedMemorySize, GEMM_SMEM);
    cudaFuncSetAttribute(mma_gemm2<true, true, false>,
                         cudaFuncAttributeMaxDynamicSharedMemorySize, GEMM_SMEM);

    // 0. concat QKV weights
    concat_w<<<(DM * 3 * DM) / 256, 256>>>(Wq, Wk, Wv, bq, bk, bv, wcat, bcat);

    // 1. LN1
    ln_kernel<<<NTOK, 256>>>(x, alpha1, beta1, n1);

    // 2. fused QKV projection: [4096,1024] @ [1024,3072] + bias
    {
        dim3 grid(3 * DM / 128, NTOK / 128, 1);
        mma_gemm2<false, true, false><<<grid, 256, GEMM_SMEM>>>(
            n1, wcat, bcat, nullptr, qkv, DM, DM, 3 * DM, 3 * DM);
    }

    // 3-5. flash attention (scores + mask + softmax + PV fused)
    {
        dim3 grid(SS / 128, HH, BB);
        flash_kernel<<<grid, 256>>>(qkv, mask, attn);
    }

    // 6. h = x + attn @ Wo + bo
    {
        dim3 grid(DM / 128, NTOK / 128, 1);
        mma_gemm2<false, true, true><<<grid, 256, GEMM_SMEM>>>(
            attn, Wo, bo, x, h, DM, DM, DM, DM);
    }

    // 7. LN2
    ln_kernel<<<NTOK, 256>>>(h, alpha2, beta2, n2);

    // 8. ffn = relu(n2 @ W1 + b1)
    {
        dim3 grid(DF / 128, NTOK / 128, 1);
        mma_gemm2<true, true, false><<<grid, 256, GEMM_SMEM>>>(
            n2, W1, b1, nullptr, ffn, DM, DM, DF, DF);
    }

    // 9. out = h + ffn @ W2 + b2
    {
        dim3 grid(DM / 128, NTOK / 128, 1);
        mma_gemm2<false, true, true><<<grid, 256, GEMM_SMEM>>>(
            ffn, W2, b2, h, out, DF, DF, DM, DM);
    }
}

// round 9
// speedup vs baseline: 4.8385x; 1.0151x over previous
#include <cuda_runtime.h>
#include <cuda_bf16.h>
#include <math.h>
#include <stdint.h>

// Problem constants
#define BB 2
#define SS 2048
#define DM 1024
#define HH 16
#define HD 64
#define DF 4096
#define NTOK (BB * SS)          // 4096
#define NEGV (-1e9f)
#define EPS 1e-6f

// ---------------------------------------------------------------------------
// Scratch (device globals — no allocation allowed)
// ---------------------------------------------------------------------------
__device__ float g_n1[NTOK * DM];
__device__ float g_qkv[(long)NTOK * 3 * DM];   // q|k|v interleaved per row
__device__ float g_wcat[DM * 3 * DM];          // Wq|Wk|Wv  [1024][3072]
__device__ float g_bcat[3 * DM];
__device__ float g_attn[NTOK * DM];
__device__ float g_h[NTOK * DM];
__device__ float g_n2[NTOK * DM];
__device__ float g_ffn[(long)NTOK * DF];

// ---------------------------------------------------------------------------
// Helpers
// ---------------------------------------------------------------------------
__device__ __forceinline__ uint32_t f2tf(float f) {
    uint32_t u;
    asm("cvt.rna.tf32.f32 %0, %1;" : "=r"(u) : "f"(f));
    return u;
}
__device__ __forceinline__ uint4 cvt4(float4 v) {
    uint4 r;
    r.x = f2tf(v.x); r.y = f2tf(v.y); r.z = f2tf(v.z); r.w = f2tf(v.w);
    return r;
}
__device__ __forceinline__ void mma_tf32(float c[4], uint32_t a0, uint32_t a1,
                                         uint32_t a2, uint32_t a3,
                                         uint32_t b0, uint32_t b1) {
    asm volatile(
        "mma.sync.aligned.m16n8k8.row.col.f32.tf32.tf32.f32 "
        "{%0,%1,%2,%3}, {%4,%5,%6,%7}, {%8,%9}, {%0,%1,%2,%3};"
        : "+f"(c[0]), "+f"(c[1]), "+f"(c[2]), "+f"(c[3])
        : "r"(a0), "r"(a1), "r"(a2), "r"(a3), "r"(b0), "r"(b1));
}
__device__ __forceinline__ void cpa16(void* dst, const void* src) {
    uint32_t d = (uint32_t)__cvta_generic_to_shared(dst);
    asm volatile("cp.async.cg.shared.global [%0], [%1], 16;" :: "r"(d), "l"(src));
}
__device__ __forceinline__ void cpa_commit() {
    asm volatile("cp.async.commit_group;" ::: "memory");
}
__device__ __forceinline__ void cpa_wait0() {
    asm volatile("cp.async.wait_group 0;" ::: "memory");
}
__device__ __forceinline__ void cpa_wait1() {
    asm volatile("cp.async.wait_group 1;" ::: "memory");
}

// ---------------------------------------------------------------------------
// Concat Wq|Wk|Wv and biases into contiguous [1024][3072] / [3072]
// ---------------------------------------------------------------------------
__global__ __launch_bounds__(256) void concat_w(
    const float* __restrict__ Wq, const float* __restrict__ Wk,
    const float* __restrict__ Wv, const float* __restrict__ bq,
    const float* __restrict__ bk, const float* __restrict__ bv,
    float* __restrict__ wcat, float* __restrict__ bcat) {
    long i = blockIdx.x * 256L + threadIdx.x;
    int row = (int)(i / (3 * DM));
    int col = (int)(i % (3 * DM));
    const float* W = (col < DM) ? Wq : ((col < 2 * DM) ? Wk : Wv);
    wcat[i] = W[row * DM + (col & (DM - 1))];
    if (i < 3 * DM) {
        const float* bb = (i < DM) ? bq : ((i < 2 * DM) ? bk : bv);
        bcat[i] = bb[i & (DM - 1)];
    }
}

// ---------------------------------------------------------------------------
// LayerNorm (torch semantics: unbiased std (ddof=1), eps added to std)
// ---------------------------------------------------------------------------
__global__ __launch_bounds__(256) void ln_kernel(const float* __restrict__ x,
                                                 const float* __restrict__ alpha,
                                                 const float* __restrict__ beta,
                                                 float* __restrict__ out) {
    long row = blockIdx.x;
    const float4* xr = (const float4*)(x + row * DM);
    float4 v = xr[threadIdx.x];

    float s  = v.x + v.y + v.z + v.w;
    float ss = v.x * v.x + v.y * v.y + v.z * v.z + v.w * v.w;

    __shared__ float sa[8], sb[8];
#pragma unroll
    for (int o = 16; o > 0; o >>= 1) {
        s  += __shfl_xor_sync(0xffffffffu, s, o);
        ss += __shfl_xor_sync(0xffffffffu, ss, o);
    }
    if ((threadIdx.x & 31) == 0) { sa[threadIdx.x >> 5] = s; sb[threadIdx.x >> 5] = ss; }
    __syncthreads();
    s = 0.f; ss = 0.f;
#pragma unroll
    for (int i = 0; i < 8; i++) { s += sa[i]; ss += sb[i]; }

    float mean = s * (1.0f / DM);
    float var  = (ss - (float)DM * mean * mean) * (1.0f / (DM - 1));
    var = fmaxf(var, 0.0f);
    float inv  = alpha[0] / (sqrtf(var) + EPS);
    float bta  = beta[0];

    float4 o;
    o.x = (v.x - mean) * inv + bta;
    o.y = (v.y - mean) * inv + bta;
    o.z = (v.z - mean) * inv + bta;
    o.w = (v.w - mean) * inv + bta;
    ((float4*)(out + row * DM))[threadIdx.x] = o;
}

// ---------------------------------------------------------------------------
// Flash attention v2: cp.async double-buffered K/V, in-place tf32 convert,
// dedicated P region (no Ksm reuse barrier).  2 barriers per 64-key tile.
// grid (S/128, H, B), 256 threads = 8 warps, 16 Q rows per warp.
// Dynamic smem (floats):
//   Kst: 2 stages x 64x76   (raw fp32 -> converted in place to tf32 bits)
//   Vst: 2 stages x 64x72
//   Pst: 8 warps x 16x36    (tf32 bits, warp-private)
//   Mst: 2 stages x 64 ints (raw mask)
//   mAddF: 2 stages x 64    (converted mask add)
// ---------------------------------------------------------------------------
#define KST 4864
#define VST 4608
#define F_KOFF 0
#define F_VOFF (2 * KST)
#define F_POFF (2 * KST + 2 * VST)
#define F_MOFF (F_POFF + 4608)
#define F_AOFF (F_MOFF + 128)
#define F_SMEM ((F_AOFF + 128) * 4)   // 95,744 B

__global__ __launch_bounds__(256, 2) void flash_kernel(
    const float* __restrict__ qkv, const int* __restrict__ mask,
    float* __restrict__ out) {
    constexpr int LDQ = 3 * DM;
    constexpr int KS = 76;
    constexpr int VS = 72;
    extern __shared__ float fsm[];
    float* Kst = fsm + F_KOFF;
    float* Vst = fsm + F_VOFF;
    uint32_t* Pst = (uint32_t*)(fsm + F_POFF);
    int* Mst = (int*)(fsm + F_MOFF);
    float* mAddF = fsm + F_AOFF;

    int qb = blockIdx.x * 128;
    int h  = blockIdx.y;
    int b  = blockIdx.z;
    const float* qp = qkv + (long)b * SS * LDQ + h * HD;
    const float* kp = qp + DM;
    const float* vp = qp + 2 * DM;
    const int* mp = mask + b * SS;

    int tid = threadIdx.x, warp = tid >> 5, lane = tid & 31;
    int g = lane >> 2, tg = lane & 3;
    int rrow = qb + warp * 16 + g;
    const int lr = tid >> 4;            // 0..15 loader row base
    const int lc = (tid & 15) * 4;      // 0..60 loader col

    // Q fragments straight from gmem (scaled by 1/sqrt(HD)=0.125, tf32)
    uint32_t qf[8][4];
#pragma unroll
    for (int ks = 0; ks < 8; ks++) {
        int c0 = ks * 8 + tg;
        qf[ks][0] = f2tf(0.125f * qp[(long)rrow * LDQ + c0]);
        qf[ks][1] = f2tf(0.125f * qp[(long)(rrow + 8) * LDQ + c0]);
        qf[ks][2] = f2tf(0.125f * qp[(long)rrow * LDQ + c0 + 4]);
        qf[ks][3] = f2tf(0.125f * qp[(long)(rrow + 8) * LDQ + c0 + 4]);
    }

    uint32_t* Psw = Pst + warp * 576;   // warp-private 16x36

    float m0 = -INFINITY, m1 = -INFINITY, l0 = 0.f, l1 = 0.f;
    float oacc[8][4];
#pragma unroll
    for (int nf = 0; nf < 8; nf++)
#pragma unroll
        for (int c = 0; c < 4; c++) oacc[nf][c] = 0.f;

    // issue tile t into stage s
    auto issue = [&](int t, int s) {
        int k0 = t * 64;
#pragma unroll
        for (int i = 0; i < 4; i++) {
            int row = lr + 16 * i;
            cpa16(Kst + s * KST + row * KS + lc, kp + (long)(k0 + row) * LDQ + lc);
            cpa16(Vst + s * VST + row * VS + lc, vp + (long)(k0 + row) * LDQ + lc);
        }
        if (tid < 16) cpa16(&Mst[s * 64 + tid * 4], &mp[k0 + tid * 4]);
        cpa_commit();
    };

    issue(0, 0);

    for (int t = 0; t < SS / 64; t++) {
        int s = t & 1;
        cpa_wait0();       // tile t landed
        __syncthreads();   // all warps done with stage s^1; tile t visible

        if (t + 1 < SS / 64) issue(t + 1, s ^ 1);

        // in-place fp32 -> tf32 conversion of stage s (same pattern as load)
        {
            float* Kp = Kst + s * KST;
            float* Vp = Vst + s * VST;
#pragma unroll
            for (int i = 0; i < 4; i++) {
                int row = lr + 16 * i;
                float4 k4 = *(float4*)(Kp + row * KS + lc);
                *(uint4*)(Kp + row * KS + lc) = cvt4(k4);
                float4 v4 = *(float4*)(Vp + row * VS + lc);
                *(uint4*)(Vp + row * VS + lc) = cvt4(v4);
            }
            if (tid < 64) mAddF[s * 64 + tid] = (Mst[s * 64 + tid] == 0) ? NEGV : 0.f;
        }
        __syncthreads();   // conversion visible

        const uint32_t* Ku = (const uint32_t*)(Kst + s * KST);
        const uint32_t* Vu = (const uint32_t*)(Vst + s * VST);
        const float* mA = mAddF + s * 64;

        // S = (Q/8) @ K^T : 16x64 per warp
        float sacc[8][4];
#pragma unroll
        for (int nf = 0; nf < 8; nf++)
#pragma unroll
            for (int c = 0; c < 4; c++) sacc[nf][c] = 0.f;
#pragma unroll
        for (int ks = 0; ks < 8; ks++) {
#pragma unroll
            for (int nf = 0; nf < 8; nf++) {
                int c = nf * 8 + g;
                uint32_t b0 = Ku[c * KS + ks * 8 + tg];
                uint32_t b1 = Ku[c * KS + ks * 8 + tg + 4];
                mma_tf32(sacc[nf], qf[ks][0], qf[ks][1], qf[ks][2], qf[ks][3], b0, b1);
            }
        }

        // mask + tile rowmax
        float tm0 = -INFINITY, tm1 = -INFINITY;
#pragma unroll
        for (int nf = 0; nf < 8; nf++) {
            float2 ma = *(const float2*)&mA[nf * 8 + 2 * tg];
            sacc[nf][0] += ma.x; sacc[nf][1] += ma.y;
            sacc[nf][2] += ma.x; sacc[nf][3] += ma.y;
            tm0 = fmaxf(tm0, fmaxf(sacc[nf][0], sacc[nf][1]));
            tm1 = fmaxf(tm1, fmaxf(sacc[nf][2], sacc[nf][3]));
        }
#pragma unroll
        for (int o = 1; o <= 2; o <<= 1) {
            tm0 = fmaxf(tm0, __shfl_xor_sync(0xffffffffu, tm0, o));
            tm1 = fmaxf(tm1, __shfl_xor_sync(0xffffffffu, tm1, o));
        }
        float nm0 = fmaxf(m0, tm0), nm1 = fmaxf(m1, tm1);
        float r0 = __expf(m0 - nm0), r1 = __expf(m1 - nm1);

        float s0 = 0.f, s1 = 0.f;
#pragma unroll
        for (int nf = 0; nf < 8; nf++) {
            sacc[nf][0] = __expf(sacc[nf][0] - nm0);
            sacc[nf][1] = __expf(sacc[nf][1] - nm0);
            sacc[nf][2] = __expf(sacc[nf][2] - nm1);
            sacc[nf][3] = __expf(sacc[nf][3] - nm1);
            s0 += sacc[nf][0] + sacc[nf][1];
            s1 += sacc[nf][2] + sacc[nf][3];
        }
#pragma unroll
        for (int o = 1; o <= 2; o <<= 1) {
            s0 += __shfl_xor_sync(0xffffffffu, s0, o);
            s1 += __shfl_xor_sync(0xffffffffu, s1, o);
        }
        l0 = l0 * r0 + s0; l1 = l1 * r1 + s1;
        m0 = nm0; m1 = nm1;
#pragma unroll
        for (int nf = 0; nf < 8; nf++) {
            oacc[nf][0] *= r0; oacc[nf][1] *= r0;
            oacc[nf][2] *= r1; oacc[nf][3] *= r1;
        }

        // O += P @ V in two 32-key halves (P chunk 16x32, stride 36, private)
#pragma unroll
        for (int half = 0; half < 2; half++) {
            __syncwarp();
#pragma unroll
            for (int nf4 = 0; nf4 < 4; nf4++) {
                int nf = half * 4 + nf4;
                *(uint2*)&Psw[g * 36 + nf4 * 8 + 2 * tg] =
                    make_uint2(f2tf(sacc[nf][0]), f2tf(sacc[nf][1]));
                *(uint2*)&Psw[(g + 8) * 36 + nf4 * 8 + 2 * tg] =
                    make_uint2(f2tf(sacc[nf][2]), f2tf(sacc[nf][3]));
            }
            __syncwarp();
#pragma unroll
            for (int ks4 = 0; ks4 < 4; ks4++) {
                int ks = half * 4 + ks4;
                uint32_t a0 = Psw[g * 36 + ks4 * 8 + tg];
                uint32_t a1 = Psw[(g + 8) * 36 + ks4 * 8 + tg];
                uint32_t a2 = Psw[g * 36 + ks4 * 8 + tg + 4];
                uint32_t a3 = Psw[(g + 8) * 36 + ks4 * 8 + tg + 4];
#pragma unroll
                for (int nf = 0; nf < 8; nf++) {
                    uint32_t b0 = Vu[(ks * 8 + tg) * VS + nf * 8 + g];
                    uint32_t b1 = Vu[(ks * 8 + tg + 4) * VS + nf * 8 + g];
                    mma_tf32(oacc[nf], a0, a1, a2, a3, b0, b1);
                }
            }
        }
    }

    // epilogue
    float i0 = 1.f / l0, i1 = 1.f / l1;
    float* op = out + (long)b * SS * DM + h * HD;
#pragma unroll
    for (int nf = 0; nf < 8; nf++) {
        int c = nf * 8 + 2 * tg;
        float2 v0 = make_float2(oacc[nf][0] * i0, oacc[nf][1] * i0);
        float2 v1 = make_float2(oacc[nf][2] * i1, oacc[nf][3] * i1);
        *(float2*)(op + (long)rrow * DM + c) = v0;
        *(float2*)(op + (long)(rrow + 8) * DM + c) = v1;
    }
}

// ---------------------------------------------------------------------------
// TF32 GEMM v2: cp.async 3-stage pipeline (R8), now 2 CTAs/SM.
// ---------------------------------------------------------------------------
template <bool RELU, bool BIAS, bool RES>
__global__ __launch_bounds__(256, 2) void mma_gemm2(
    const float* __restrict__ A, const float* __restrict__ Bm,
    const float* __restrict__ bias, const float* __restrict__ res,
    float* __restrict__ C, int K, int lda, int ldb, int ldc) {
    constexpr int BK = 32, AS = 36, BS = 136;
    constexpr int ASTG = 128 * AS;
    constexpr int BSTG = BK * BS;

    extern __shared__ float smem[];
    float* Asm = smem;
    float* Bsm = smem + 3 * ASTG;

    int bm = blockIdx.y * 128;
    int bn = blockIdx.x * 128;
    int tid = threadIdx.x, warp = tid >> 5, lane = tid & 31;
    int g = lane >> 2, tg = lane & 3;
    int wm = warp >> 2, wn = warp & 3;

    const int am = tid >> 3;
    const int ak = (tid & 7) * 4;
    const int bk_ = tid >> 5;
    const int bn_ = (tid & 31) * 4;
    const int nT = K / BK;

    const float* Agp = A + (long)(bm + am) * lda + ak;
    const float* Bgp = Bm + (long)bk_ * ldb + bn + bn_;
    float* Aw = Asm + am * AS + ak;
    float* Bw = Bsm + bk_ * BS + bn_;

#pragma unroll
    for (int p = 0; p < 2; p++) {
#pragma unroll
        for (int i = 0; i < 4; i++)
            cpa16(Aw + p * ASTG + 32 * i * AS, Agp + (long)32 * i * lda + p * BK);
#pragma unroll
        for (int i = 0; i < 4; i++)
            cpa16(Bw + p * BSTG + 8 * i * BS, Bgp + (long)(p * BK + 8 * i) * ldb);
        cpa_commit();
    }

    float acc[4][4][4];
#pragma unroll
    for (int i = 0; i < 4; i++)
#pragma unroll
        for (int j = 0; j < 4; j++)
#pragma unroll
            for (int c = 0; c < 4; c++) acc[i][j][c] = 0.f;

    for (int t = 0; t < nT; t++) {
        cpa_wait1();
        __syncthreads();

        if (t + 2 < nT) {
            int slot = (t + 2) % 3;
            int k0 = (t + 2) * BK;
#pragma unroll
            for (int i = 0; i < 4; i++)
                cpa16(Aw + slot * ASTG + 32 * i * AS, Agp + (long)32 * i * lda + k0);
#pragma unroll
            for (int i = 0; i < 4; i++)
                cpa16(Bw + slot * BSTG + 8 * i * BS, Bgp + (long)(k0 + 8 * i) * ldb);
        }
        cpa_commit();

        const float* As = Asm + (t % 3) * ASTG;
        const float* Bs = Bsm + (t % 3) * BSTG;

#pragma unroll
        for (int ks = 0; ks < 4; ks++) {
            uint32_t af[4][4];
            uint32_t bf[4][2];
#pragma unroll
            for (int mt = 0; mt < 4; mt++) {
                int r = wm * 64 + mt * 16 + g;
                af[mt][0] = f2tf(As[r * AS + ks * 8 + tg]);
                af[mt][1] = f2tf(As[(r + 8) * AS + ks * 8 + tg]);
                af[mt][2] = f2tf(As[r * AS + ks * 8 + tg + 4]);
                af[mt][3] = f2tf(As[(r + 8) * AS + ks * 8 + tg + 4]);
            }
#pragma unroll
            for (int nt = 0; nt < 4; nt++) {
                int c = wn * 32 + nt * 8 + g;
                bf[nt][0] = f2tf(Bs[(ks * 8 + tg) * BS + c]);
                bf[nt][1] = f2tf(Bs[(ks * 8 + tg + 4) * BS + c]);
            }
#pragma unroll
            for (int mt = 0; mt < 4; mt++)
#pragma unroll
                for (int nt = 0; nt < 4; nt++)
                    mma_tf32(acc[mt][nt], af[mt][0], af[mt][1], af[mt][2], af[mt][3],
                             bf[nt][0], bf[nt][1]);
        }
    }

#pragma unroll
    for (int mt = 0; mt < 4; mt++) {
        int r = bm + wm * 64 + mt * 16 + g;
#pragma unroll
        for (int nt = 0; nt < 4; nt++) {
            int c = bn + wn * 32 + nt * 8 + tg * 2;
            float2 v0, v1;
            v0.x = acc[mt][nt][0]; v0.y = acc[mt][nt][1];
            v1.x = acc[mt][nt][2]; v1.y = acc[mt][nt][3];
            if (BIAS) {
                float2 bv = *(const float2*)(bias + c);
                v0.x += bv.x; v0.y += bv.y; v1.x += bv.x; v1.y += bv.y;
            }
            if (RELU) {
                v0.x = fmaxf(v0.x, 0.f); v0.y = fmaxf(v0.y, 0.f);
                v1.x = fmaxf(v1.x, 0.f); v1.y = fmaxf(v1.y, 0.f);
            }
            if (RES) {
                float2 r0 = *(const float2*)(res + (long)r * ldc + c);
                float2 r1 = *(const float2*)(res + (long)(r + 8) * ldc + c);
                v0.x += r0.x; v0.y += r0.y; v1.x += r1.x; v1.y += r1.y;
            }
            *(float2*)(C + (long)r * ldc + c) = v0;
            *(float2*)(C + (long)(r + 8) * ldc + c) = v1;
        }
    }
}

// ---------------------------------------------------------------------------
// Host side
// ---------------------------------------------------------------------------
template <typename T>
static float* sym(const T& s) {
    void* p = nullptr;
    cudaGetSymbolAddress(&p, s);
    return (float*)p;
}

#define GEMM_SMEM 107520

extern "C" void kernel_launch(void* const* d_in, const int* in_sizes, int n_in,
                              void* d_out, int out_size) {
    const float* x      = (const float*)d_in[0];
    const int*   mask   = (const int*)d_in[1];
    const float* Wq     = (const float*)d_in[2];
    const float* bq     = (const float*)d_in[3];
    const float* Wk     = (const float*)d_in[4];
    const float* bk     = (const float*)d_in[5];
    const float* Wv     = (const float*)d_in[6];
    const float* bv     = (const float*)d_in[7];
    const float* Wo     = (const float*)d_in[8];
    const float* bo     = (const float*)d_in[9];
    const float* W1     = (const float*)d_in[10];
    const float* b1     = (const float*)d_in[11];
    const float* W2     = (const float*)d_in[12];
    const float* b2     = (const float*)d_in[13];
    const float* alpha1 = (const float*)d_in[14];
    const float* beta1  = (const float*)d_in[15];
    const float* alpha2 = (const float*)d_in[16];
    const float* beta2  = (const float*)d_in[17];
    float* out = (float*)d_out;

    float* n1   = sym(g_n1);
    float* qkv  = sym(g_qkv);
    float* wcat = sym(g_wcat);
    float* bcat = sym(g_bcat);
    float* attn = sym(g_attn);
    float* h    = sym(g_h);
    float* n2   = sym(g_n2);
    float* ffn  = sym(g_ffn);

    // opt-in to >48KB dynamic smem (idempotent)
    cudaFuncSetAttribute(mma_gemm2<false, true, false>,
                         cudaFuncAttributeMaxDynamicSharedMemorySize, GEMM_SMEM);
    cudaFuncSetAttribute(mma_gemm2<false, true, true>,
                         cudaFuncAttributeMaxDynamicSharedMemorySize, GEMM_SMEM);
    cudaFuncSetAttribute(mma_gemm2<true, true, false>,
                         cudaFuncAttributeMaxDynamicSharedMemorySize, GEMM_SMEM);
    cudaFuncSetAttribute(flash_kernel,
                         cudaFuncAttributeMaxDynamicSharedMemorySize, F_SMEM);

    // 0. concat QKV weights
    concat_w<<<(DM * 3 * DM) / 256, 256>>>(Wq, Wk, Wv, bq, bk, bv, wcat, bcat);

    // 1. LN1
    ln_kernel<<<NTOK, 256>>>(x, alpha1, beta1, n1);

    // 2. fused QKV projection: [4096,1024] @ [1024,3072] + bias
    {
        dim3 grid(3 * DM / 128, NTOK / 128, 1);
        mma_gemm2<false, true, false><<<grid, 256, GEMM_SMEM>>>(
            n1, wcat, bcat, nullptr, qkv, DM, DM, 3 * DM, 3 * DM);
    }

    // 3-5. flash attention
    {
        dim3 grid(SS / 128, HH, BB);
        flash_kernel<<<grid, 256, F_SMEM>>>(qkv, mask, attn);
    }

    // 6. h = x + attn @ Wo + bo
    {
        dim3 grid(DM / 128, NTOK / 128, 1);
        mma_gemm2<false, true, true><<<grid, 256, GEMM_SMEM>>>(
            attn, Wo, bo, x, h, DM, DM, DM, DM);
    }

    // 7. LN2
    ln_kernel<<<NTOK, 256>>>(h, alpha2, beta2, n2);

    // 8. ffn = relu(n2 @ W1 + b1)
    {
        dim3 grid(DF / 128, NTOK / 128, 1);
        mma_gemm2<true, true, false><<<grid, 256, GEMM_SMEM>>>(
            n2, W1, b1, nullptr, ffn, DM, DM, DF, DF);
    }

    // 9. out = h + ffn @ W2 + b2
    {
        dim3 grid(DM / 128, NTOK / 128, 1);
        mma_gemm2<false, true, true><<<grid, 256, GEMM_SMEM>>>(
            ffn, W2, b2, h, out, DF, DF, DM, DM);
    }
}